// round 3
// baseline (speedup 1.0000x reference)
#include <cuda_runtime.h>
#include <math.h>

#define K_VOX 40000
#define T_PTS 35
#define C_IN  7
#define U1    16
#define U2    32
#define DD    10
#define HH    400
#define WW    352
#define NROWS (K_VOX * T_PTS)
#define EPSBN 1e-5f

#define NCOMP 148            // compute blocks
#define NZERO 148            // zeroing blocks
#define NBLK_TOT (NCOMP + NZERO)
#define BTHR  128            // threads per block
#define BW    4              // warps per block
#define H1S   20             // h1 row stride (floats), conflict-free float4

// ---------------- global scratch (static, allocation-free) ----------------
__device__ float    g_sum1[U1], g_sq1[U1];
__device__ float    g_sum2[U2], g_sq2[U2];
__device__ unsigned g_bar1, g_bar2;
__device__ unsigned g_zctr;
__device__ float    g_vox[(size_t)K_VOX * 4 * U2];  // [v][{Mx,Mn,Mx1,Mn1}][32]
__device__ int      g_flags[K_VOX];                 // bit0 anyM, bit1 allM

__global__ void reset_kernel() {
    int t = threadIdx.x;
    if (t < U1) { g_sum1[t] = 0.f; g_sq1[t] = 0.f; }
    if (t < U2) { g_sum2[t] = 0.f; g_sq2[t] = 0.f; }
    if (t == 0) { g_bar1 = 0u; g_bar2 = 0u; g_zctr = 0u; }
}

__device__ __forceinline__ void bar_arrive_wait(unsigned* ctr, unsigned target) {
    __syncthreads();
    if (threadIdx.x == 0) {
        __threadfence();
        atomicAdd(ctr, 1u);
        while (*((volatile unsigned*)ctr) < target) { }
        __threadfence();
    }
    __syncthreads();
}

// streaming float4 zero store
__device__ __forceinline__ void stz(float4* p) {
    asm volatile("st.global.cs.v4.f32 [%0], {%1,%1,%1,%1};"
                 :: "l"(p), "f"(0.0f) : "memory");
}

// grab 64KB chunks (4096 float4) until exhausted
__device__ __forceinline__ void zero_chunks(float4* o4, unsigned n4, int lane) {
    for (;;) {
        unsigned c;
        if (lane == 0) c = atomicAdd(&g_zctr, 1u);
        c = __shfl_sync(0xFFFFFFFFu, c, 0);
        size_t base = (size_t)c * 4096;
        if (base >= n4) break;
        if (base + 4096 <= n4) {
#pragma unroll 4
            for (int i = 0; i < 128; i++)
                stz(o4 + base + (size_t)i * 32 + lane);
        } else {
            for (size_t i = base + lane; i < n4; i += 32)
                stz(o4 + i);
        }
    }
}

__global__ void __launch_bounds__(BTHR, 2)
fused_kernel(const float* __restrict__ feat,
             const float* __restrict__ w1,  const float* __restrict__ b1,
             const float* __restrict__ g1,  const float* __restrict__ be1,
             const float* __restrict__ w2,  const float* __restrict__ b2,
             const float* __restrict__ g2,  const float* __restrict__ be2,
             const int*   __restrict__ coord,
             float*       __restrict__ out, int out_size) {
    __shared__ float sw1[C_IN * U1];
    __shared__ float sb1[U1];
    __shared__ float s_sc1[U1], s_sh1[U1];
    __shared__ float s_sc2[U2], s_sh2[U2];
    __shared__ float ssum[U1], ssq[U1];
    __shared__ float s_h1[BW][T_PTS][H1S];
    __shared__ float s_mask[BW][T_PTS];
    __shared__ float s_agg[BW][U1];

    const int tid  = threadIdx.x;
    const int w    = tid >> 5;
    const int lane = tid & 31;
    const int bid  = blockIdx.x;
    const float invN = 1.0f / (float)NROWS;
    const unsigned n4 = (unsigned)(out_size >> 2);   // out_size % 4 == 0
    float4* o4 = (float4*)out;

    if (bid >= NCOMP) {
        // ================== ZERO ROLE: stream zeros from t=0 ==================
        zero_chunks(o4, n4, lane);
        bar_arrive_wait(&g_bar2, NBLK_TOT);
    } else {
        // ================== COMPUTE ROLE ==================
        if (tid < C_IN * U1) sw1[tid] = w1[tid];
        if (tid < U1) { sb1[tid] = b1[tid]; ssum[tid] = 0.f; ssq[tid] = 0.f; }
        __syncthreads();

        // ---- stage 1: BN1 statistics (compute blocks only) ----
        {
            float psum[U1], psq[U1];
#pragma unroll
            for (int u = 0; u < U1; u++) { psum[u] = 0.f; psq[u] = 0.f; }
            for (int r = bid * BTHR + tid; r < NROWS; r += NCOMP * BTHR) {
                const float* fp = feat + (size_t)r * C_IN;
                float f[C_IN];
#pragma unroll
                for (int c = 0; c < C_IN; c++) f[c] = fp[c];
#pragma unroll
                for (int u = 0; u < U1; u++) {
                    float a = sb1[u];
#pragma unroll
                    for (int c = 0; c < C_IN; c++) a = fmaf(f[c], sw1[c * U1 + u], a);
                    a = fmaxf(a, 0.f);
                    psum[u] += a;
                    psq [u]  = fmaf(a, a, psq[u]);
                }
            }
#pragma unroll
            for (int u = 0; u < U1; u++) {
#pragma unroll
                for (int o = 16; o > 0; o >>= 1) {
                    psum[u] += __shfl_down_sync(0xFFFFFFFFu, psum[u], o);
                    psq [u] += __shfl_down_sync(0xFFFFFFFFu, psq [u], o);
                }
                if (lane == 0) { atomicAdd(&ssum[u], psum[u]); atomicAdd(&ssq[u], psq[u]); }
            }
            __syncthreads();
            if (tid < U1) {
                atomicAdd(&g_sum1[tid], ssum[tid]);
                atomicAdd(&g_sq1 [tid], ssq [tid]);
            }
        }
        bar_arrive_wait(&g_bar1, NCOMP);

        if (tid < U1) {
            float mean = __ldcg(&g_sum1[tid]) * invN;
            float var  = __ldcg(&g_sq1 [tid]) * invN - mean * mean;
            float sc   = rsqrtf(var + EPSBN) * g1[tid];
            s_sc1[tid] = sc;
            s_sh1[tid] = be1[tid] - mean * sc;
        }
        __syncthreads();

        // ---- stage 2: voxel pass (one warp per voxel) ----
        float wcol[U2];
#pragma unroll
        for (int i = 0; i < U2; i++) wcol[i] = w2[i * U2 + lane];
        const float b2l = b2[lane];
        float vsum = 0.f, vsq = 0.f;

        for (int v = bid * BW + w; v < K_VOX; v += NCOMP * BW) {
            const float* fv = feat + (size_t)v * T_PTS * C_IN;
            unsigned mb0, mb1;
            {   // t = lane (all 32 valid)
                const float* fp = fv + lane * C_IN;
                float f[C_IN]; float mx = -INFINITY;
#pragma unroll
                for (int c = 0; c < C_IN; c++) { f[c] = fp[c]; mx = fmaxf(mx, f[c]); }
                float m = (mx != 0.0f) ? 1.0f : 0.0f;
                mb0 = __ballot_sync(0xFFFFFFFFu, m != 0.0f);
                s_mask[w][lane] = m;
                float h[U1];
#pragma unroll
                for (int u = 0; u < U1; u++) {
                    float a = sb1[u];
#pragma unroll
                    for (int c = 0; c < C_IN; c++) a = fmaf(f[c], sw1[c * U1 + u], a);
                    a = fmaxf(a, 0.f);
                    h[u] = fmaf(a, s_sc1[u], s_sh1[u]);
                }
                float4* row = (float4*)&s_h1[w][lane][0];
                row[0] = make_float4(h[0],  h[1],  h[2],  h[3]);
                row[1] = make_float4(h[4],  h[5],  h[6],  h[7]);
                row[2] = make_float4(h[8],  h[9],  h[10], h[11]);
                row[3] = make_float4(h[12], h[13], h[14], h[15]);
            }
            {   // t = 32 + lane (3 valid)
                int t = 32 + lane;
                bool act = (lane < (T_PTS - 32));
                float m = 0.0f;
                float f[C_IN];
                if (act) {
                    const float* fp = fv + t * C_IN;
                    float mx = -INFINITY;
#pragma unroll
                    for (int c = 0; c < C_IN; c++) { f[c] = fp[c]; mx = fmaxf(mx, f[c]); }
                    m = (mx != 0.0f) ? 1.0f : 0.0f;
                }
                mb1 = __ballot_sync(0xFFFFFFFFu, act && (m != 0.0f));
                if (act) {
                    s_mask[w][t] = m;
                    float h[U1];
#pragma unroll
                    for (int u = 0; u < U1; u++) {
                        float a = sb1[u];
#pragma unroll
                        for (int c = 0; c < C_IN; c++) a = fmaf(f[c], sw1[c * U1 + u], a);
                        a = fmaxf(a, 0.f);
                        h[u] = fmaf(a, s_sc1[u], s_sh1[u]);
                    }
                    float4* row = (float4*)&s_h1[w][t][0];
                    row[0] = make_float4(h[0],  h[1],  h[2],  h[3]);
                    row[1] = make_float4(h[4],  h[5],  h[6],  h[7]);
                    row[2] = make_float4(h[8],  h[9],  h[10], h[11]);
                    row[3] = make_float4(h[12], h[13], h[14], h[15]);
                }
            }
            const bool anyM = ((mb0 | (mb1 & 7u)) != 0u);
            const bool allM = (mb0 == 0xFFFFFFFFu) && ((mb1 & 7u) == 7u);
            __syncwarp();

            if (lane < U1) {
                float mx = -INFINITY;
                for (int t = 0; t < T_PTS; t++) mx = fmaxf(mx, s_h1[w][t][lane]);
                s_agg[w][lane] = mx;
            }
            __syncwarp();

            float aggdot = 0.f;
#pragma unroll
            for (int j = 0; j < U1; j++)
                aggdot = fmaf(s_agg[w][j], wcol[U1 + j], aggdot);

            float Mx = -INFINITY, Mn = INFINITY, Mx1 = -INFINITY, Mn1 = INFINITY;
#pragma unroll 5
            for (int t = 0; t < T_PTS; t++) {
                const float4* row = (const float4*)&s_h1[w][t][0];
                float4 a0 = row[0], a1 = row[1], a2 = row[2], a3 = row[3];
                float d0 = a0.x * wcol[0];
                float d1 = a0.y * wcol[1];
                d0 = fmaf(a0.z, wcol[2],  d0); d1 = fmaf(a0.w, wcol[3],  d1);
                d0 = fmaf(a1.x, wcol[4],  d0); d1 = fmaf(a1.y, wcol[5],  d1);
                d0 = fmaf(a1.z, wcol[6],  d0); d1 = fmaf(a1.w, wcol[7],  d1);
                d0 = fmaf(a2.x, wcol[8],  d0); d1 = fmaf(a2.y, wcol[9],  d1);
                d0 = fmaf(a2.z, wcol[10], d0); d1 = fmaf(a2.w, wcol[11], d1);
                d0 = fmaf(a3.x, wcol[12], d0); d1 = fmaf(a3.y, wcol[13], d1);
                d0 = fmaf(a3.z, wcol[14], d0); d1 = fmaf(a3.w, wcol[15], d1);
                float m  = s_mask[w][t];
                float h2 = fmaxf(fmaf(m, d0 + d1 + aggdot, b2l), 0.f);
                vsum += h2;
                vsq   = fmaf(h2, h2, vsq);
                Mx = fmaxf(Mx, h2);
                Mn = fminf(Mn, h2);
                bool mb = (m != 0.f);
                Mx1 = fmaxf(Mx1, mb ? h2 : -INFINITY);
                Mn1 = fminf(Mn1, mb ? h2 :  INFINITY);
            }

            float* gv = g_vox + (size_t)v * (4 * U2);
            gv[lane]          = Mx;
            gv[U2 + lane]     = Mn;
            gv[2 * U2 + lane] = Mx1;
            gv[3 * U2 + lane] = Mn1;
            if (lane == 0) g_flags[v] = (anyM ? 1 : 0) | (allM ? 2 : 0);
        }
        atomicAdd(&g_sum2[lane], vsum);
        atomicAdd(&g_sq2 [lane], vsq);

        // compute done -> steal zero chunks until the grid is fully zeroed
        zero_chunks(o4, n4, lane);
        bar_arrive_wait(&g_bar2, NBLK_TOT);
    }

    // ================= stage 3: finalize BN2 + scatter (all blocks) =================
    if (tid < U2) {
        float mean = __ldcg(&g_sum2[tid]) * invN;
        float var  = __ldcg(&g_sq2 [tid]) * invN - mean * mean;
        float sc   = rsqrtf(var + EPSBN) * g2[tid];
        s_sc2[tid] = sc;
        s_sh2[tid] = be2[tid] - mean * sc;
    }
    __syncthreads();

    {
        const float sc = s_sc2[lane];
        const float sh = s_sh2[lane];
        for (int v = bid * BW + w; v < K_VOX; v += NBLK_TOT * BW) {
            const float* gv = g_vox + (size_t)v * (4 * U2);
            float Mx  = __ldcg(gv + lane);
            float Mn  = __ldcg(gv + U2 + lane);
            float Mx1 = __ldcg(gv + 2 * U2 + lane);
            float Mn1 = __ldcg(gv + 3 * U2 + lane);
            int   fl  = g_flags[v];
            bool anyM = (fl & 1) != 0;
            bool allM = (fl & 2) != 0;

            float agg2 = fmaf((sc >= 0.f) ? Mx  : Mn,  sc, sh);
            float mskd = fmaf((sc >= 0.f) ? Mx1 : Mn1, sc, sh);

            float vwlo = anyM ? mskd : -INFINITY;
            float vwhi = anyM ? agg2 : -INFINITY;
            if (!allM) { vwlo = fmaxf(vwlo, 0.f); vwhi = fmaxf(vwhi, 0.f); }

            const int* cp = coord + (size_t)v * 4;
            size_t base = ((((size_t)cp[0] * DD + cp[1]) * HH + cp[2]) * WW + cp[3]) * (size_t)(2 * U2);
            atomicAdd(out + base + lane,      vwlo);
            atomicAdd(out + base + U2 + lane, vwhi);
        }
    }
}

// ---------------- launch ----------------
extern "C" void kernel_launch(void* const* d_in, const int* in_sizes, int n_in,
                              void* d_out, int out_size) {
    const float* feat  = (const float*)d_in[0];
    const float* w1    = (const float*)d_in[1];
    const float* b1    = (const float*)d_in[2];
    const float* g1    = (const float*)d_in[3];
    const float* be1   = (const float*)d_in[4];
    const float* w2    = (const float*)d_in[5];
    const float* b2    = (const float*)d_in[6];
    const float* g2    = (const float*)d_in[7];
    const float* be2   = (const float*)d_in[8];
    const int*   coord = (const int*)  d_in[9];
    float* out = (float*)d_out;

    reset_kernel<<<1, 64>>>();
    fused_kernel<<<NBLK_TOT, BTHR>>>(feat, w1, b1, g1, be1,
                                     w2, b2, g2, be2, coord, out, out_size);
}

// round 4
// speedup vs baseline: 1.0186x; 1.0186x over previous
#include <cuda_runtime.h>
#include <math.h>

#define K_VOX 40000
#define T_PTS 35
#define C_IN  7
#define U1    16
#define U2    32
#define DD    10
#define HH    400
#define WW    352
#define NROWS (K_VOX * T_PTS)
#define EPSBN 1e-5f

#define NBLK   148
#define BTHR   256
#define CWARPS 4             // compute warps per block
#define CTHR   (CWARPS * 32)
#define H1S    20            // h1 row stride (floats), 16B-aligned rows

// ---------------- global scratch (static, allocation-free) ----------------
__device__ float    g_sum1[U1], g_sq1[U1];
__device__ float    g_sum2[U2], g_sq2[U2];
__device__ unsigned g_bar1, g_bar2;
__device__ unsigned g_zctr;
__device__ float    g_vox[(size_t)K_VOX * 4 * U2];  // [v][{Mx,Mn,Mx1,Mn1}][32]
__device__ int      g_flags[K_VOX];                 // bit0 anyM, bit1 allM

__global__ void reset_kernel() {
    int t = threadIdx.x;
    if (t < U1) { g_sum1[t] = 0.f; g_sq1[t] = 0.f; }
    if (t < U2) { g_sum2[t] = 0.f; g_sq2[t] = 0.f; }
    if (t == 0) { g_bar1 = 0u; g_bar2 = 0u; g_zctr = 0u; }
}

// named barrier over the compute warps only (threads 0..CTHR-1)
__device__ __forceinline__ void barc() {
    asm volatile("bar.sync 1, %0;" :: "r"(CTHR) : "memory");
}

// compute-warp grid barrier (zero warps keep streaming meanwhile)
__device__ __forceinline__ void cbar(unsigned* ctr, unsigned target) {
    barc();
    if (threadIdx.x == 0) {
        __threadfence();
        atomicAdd(ctr, 1u);
        while (*((volatile unsigned*)ctr) < target) { }
        __threadfence();
    }
    barc();
}

// zero 32KB chunks (2048 float4) grabbed from a global counter; plain stores
__device__ __forceinline__ void zero_chunks(float4* o4, unsigned n4, int lane) {
    const float4 z = make_float4(0.f, 0.f, 0.f, 0.f);
    for (;;) {
        unsigned c;
        if (lane == 0) c = atomicAdd(&g_zctr, 1u);
        c = __shfl_sync(0xFFFFFFFFu, c, 0);
        size_t base = (size_t)c * 2048;
        if (base >= n4) break;
        if (base + 2048 <= n4) {
            float4* p = o4 + base + lane;
#pragma unroll
            for (int i = 0; i < 64; i++) p[(size_t)i * 32] = z;   // STG.128 [reg+imm]
        } else {
            for (size_t i = base + lane; i < n4; i += 32) o4[i] = z;
        }
    }
}

__global__ void __launch_bounds__(BTHR, 1)
fused_kernel(const float* __restrict__ feat,
             const float* __restrict__ w1,  const float* __restrict__ b1,
             const float* __restrict__ g1,  const float* __restrict__ be1,
             const float* __restrict__ w2,  const float* __restrict__ b2,
             const float* __restrict__ g2,  const float* __restrict__ be2,
             const int*   __restrict__ coord,
             float*       __restrict__ out, int out_size) {
    __shared__ float sw1[C_IN * U1];
    __shared__ float sb1[U1];
    __shared__ float s_sc1[U1], s_sh1[U1], s_h1z[U1];
    __shared__ float s_sc2[U2], s_sh2[U2];
    __shared__ float ssum[U1], ssq[U1];
    __shared__ float s_h1[CWARPS][T_PTS][H1S];
    __shared__ float s_agg[CWARPS][U1];

    const int tid  = threadIdx.x;
    const int w    = tid >> 5;
    const int lane = tid & 31;
    const int bid  = blockIdx.x;
    const float invN = 1.0f / (float)NROWS;
    const unsigned n4 = (unsigned)(out_size >> 2);
    float4* o4 = (float4*)out;

    if (w >= CWARPS) {
        // ============ ZERO ROLE: stream zeros from t=0 ============
        zero_chunks(o4, n4, lane);
    } else {
        // ============ COMPUTE ROLE ============
        if (tid < C_IN * U1) sw1[tid] = w1[tid];
        if (tid < U1) { sb1[tid] = b1[tid]; ssum[tid] = 0.f; ssq[tid] = 0.f; }
        barc();

        // ---- stage 1: BN1 statistics ----
        {
            float psum[U1], psq[U1];
#pragma unroll
            for (int u = 0; u < U1; u++) { psum[u] = 0.f; psq[u] = 0.f; }
            for (int r = bid * CTHR + tid; r < NROWS; r += NBLK * CTHR) {
                const float* fp = feat + (size_t)r * C_IN;
                float f[C_IN];
#pragma unroll
                for (int c = 0; c < C_IN; c++) f[c] = fp[c];
#pragma unroll
                for (int u = 0; u < U1; u++) {
                    float a = sb1[u];
#pragma unroll
                    for (int c = 0; c < C_IN; c++) a = fmaf(f[c], sw1[c * U1 + u], a);
                    a = fmaxf(a, 0.f);
                    psum[u] += a;
                    psq [u]  = fmaf(a, a, psq[u]);
                }
            }
#pragma unroll
            for (int u = 0; u < U1; u++) {
#pragma unroll
                for (int o = 16; o > 0; o >>= 1) {
                    psum[u] += __shfl_down_sync(0xFFFFFFFFu, psum[u], o);
                    psq [u] += __shfl_down_sync(0xFFFFFFFFu, psq [u], o);
                }
                if (lane == 0) { atomicAdd(&ssum[u], psum[u]); atomicAdd(&ssq[u], psq[u]); }
            }
            barc();
            if (tid < U1) {
                atomicAdd(&g_sum1[tid], ssum[tid]);
                atomicAdd(&g_sq1 [tid], ssq [tid]);
            }
        }
        cbar(&g_bar1, NBLK);

        if (tid < U1) {
            float mean = __ldcg(&g_sum1[tid]) * invN;
            float var  = __ldcg(&g_sq1 [tid]) * invN - mean * mean;
            float sc   = rsqrtf(var + EPSBN) * g1[tid];
            s_sc1[tid] = sc;
            s_sh1[tid] = be1[tid] - mean * sc;
            s_h1z[tid] = fmaf(fmaxf(sb1[tid], 0.f), sc, be1[tid] - mean * sc);
        }
        barc();

        // ---- stage 2: voxel pass (one warp per voxel, masked-row compaction) ----
        float wcol[U2];
#pragma unroll
        for (int i = 0; i < U2; i++) wcol[i] = w2[i * U2 + lane];
        const float b2l = b2[lane];
        const float h2z = fmaxf(b2l, 0.f);     // h2 of a masked-out point (pre-BN)
        float vsum = 0.f, vsq = 0.f;

        for (int v = bid * CWARPS + w; v < K_VOX; v += NBLK * CWARPS) {
            const float* fv = feat + (size_t)v * T_PTS * C_IN;
            unsigned mb0, mb1;
            {   // t = lane (32 rows)
                const float* fp = fv + lane * C_IN;
                float f[C_IN]; float mx = -INFINITY;
#pragma unroll
                for (int c = 0; c < C_IN; c++) { f[c] = fp[c]; mx = fmaxf(mx, f[c]); }
                bool msk = (mx != 0.0f);
                mb0 = __ballot_sync(0xFFFFFFFFu, msk);
                if (msk) {
                    int rank = __popc(mb0 & ((1u << lane) - 1u));
                    float h[U1];
#pragma unroll
                    for (int u = 0; u < U1; u++) {
                        float a = sb1[u];
#pragma unroll
                        for (int c = 0; c < C_IN; c++) a = fmaf(f[c], sw1[c * U1 + u], a);
                        a = fmaxf(a, 0.f);
                        h[u] = fmaf(a, s_sc1[u], s_sh1[u]);
                    }
                    float4* row = (float4*)&s_h1[w][rank][0];
                    row[0] = make_float4(h[0],  h[1],  h[2],  h[3]);
                    row[1] = make_float4(h[4],  h[5],  h[6],  h[7]);
                    row[2] = make_float4(h[8],  h[9],  h[10], h[11]);
                    row[3] = make_float4(h[12], h[13], h[14], h[15]);
                }
            }
            {   // t = 32 + lane (3 rows)
                bool act = (lane < (T_PTS - 32));
                float f[C_IN]; float mx = -INFINITY;
                if (act) {
                    const float* fp = fv + (32 + lane) * C_IN;
#pragma unroll
                    for (int c = 0; c < C_IN; c++) { f[c] = fp[c]; mx = fmaxf(mx, f[c]); }
                }
                bool msk = act && (mx != 0.0f);
                mb1 = __ballot_sync(0xFFFFFFFFu, msk);
                if (msk) {
                    int rank = __popc(mb0) + __popc(mb1 & ((1u << lane) - 1u));
                    float h[U1];
#pragma unroll
                    for (int u = 0; u < U1; u++) {
                        float a = sb1[u];
#pragma unroll
                        for (int c = 0; c < C_IN; c++) a = fmaf(f[c], sw1[c * U1 + u], a);
                        a = fmaxf(a, 0.f);
                        h[u] = fmaf(a, s_sc1[u], s_sh1[u]);
                    }
                    float4* row = (float4*)&s_h1[w][rank][0];
                    row[0] = make_float4(h[0],  h[1],  h[2],  h[3]);
                    row[1] = make_float4(h[4],  h[5],  h[6],  h[7]);
                    row[2] = make_float4(h[8],  h[9],  h[10], h[11]);
                    row[3] = make_float4(h[12], h[13], h[14], h[15]);
                }
            }
            const int nm = __popc(mb0) + __popc(mb1);
            const int nz = T_PTS - nm;
            __syncwarp();

            // agg1 over all t = max(compact rows, h1z if any zero row)
            if (lane < U1) {
                float mx = (nz > 0) ? s_h1z[lane] : -INFINITY;
                for (int r = 0; r < nm; r++) mx = fmaxf(mx, s_h1[w][r][lane]);
                s_agg[w][lane] = mx;
            }
            __syncwarp();

            float aggdot = b2l;
#pragma unroll
            for (int j = 0; j < U1; j++)
                aggdot = fmaf(s_agg[w][j], wcol[U1 + j], aggdot);
            // aggdot now includes bias: h2(row) = relu(dot(h1,wcol) + aggdot)

            float Mx, Mn;
            if (nz > 0) { Mx = h2z; Mn = h2z; } else { Mx = -INFINITY; Mn = INFINITY; }
            float Mx1 = -INFINITY, Mn1 = INFINITY;
            float fz = (float)nz;
            vsum += fz * h2z;
            vsq   = fmaf(fz, h2z * h2z, vsq);

            int r = 0;
            for (; r + 2 <= nm; r += 2) {
                const float4* ra = (const float4*)&s_h1[w][r][0];
                const float4* rb = (const float4*)&s_h1[w][r + 1][0];
                float4 a0 = ra[0], a1 = ra[1], a2 = ra[2], a3 = ra[3];
                float4 c0 = rb[0], c1 = rb[1], c2 = rb[2], c3 = rb[3];
                float d0 = fmaf(a0.x, wcol[0], 0.f), d1 = fmaf(a0.y, wcol[1], 0.f);
                float e0 = fmaf(c0.x, wcol[0], 0.f), e1 = fmaf(c0.y, wcol[1], 0.f);
                d0 = fmaf(a0.z, wcol[2],  d0); d1 = fmaf(a0.w, wcol[3],  d1);
                e0 = fmaf(c0.z, wcol[2],  e0); e1 = fmaf(c0.w, wcol[3],  e1);
                d0 = fmaf(a1.x, wcol[4],  d0); d1 = fmaf(a1.y, wcol[5],  d1);
                e0 = fmaf(c1.x, wcol[4],  e0); e1 = fmaf(c1.y, wcol[5],  e1);
                d0 = fmaf(a1.z, wcol[6],  d0); d1 = fmaf(a1.w, wcol[7],  d1);
                e0 = fmaf(c1.z, wcol[6],  e0); e1 = fmaf(c1.w, wcol[7],  e1);
                d0 = fmaf(a2.x, wcol[8],  d0); d1 = fmaf(a2.y, wcol[9],  d1);
                e0 = fmaf(c2.x, wcol[8],  e0); e1 = fmaf(c2.y, wcol[9],  e1);
                d0 = fmaf(a2.z, wcol[10], d0); d1 = fmaf(a2.w, wcol[11], d1);
                e0 = fmaf(c2.z, wcol[10], e0); e1 = fmaf(c2.w, wcol[11], e1);
                d0 = fmaf(a3.x, wcol[12], d0); d1 = fmaf(a3.y, wcol[13], d1);
                e0 = fmaf(c3.x, wcol[12], e0); e1 = fmaf(c3.y, wcol[13], e1);
                d0 = fmaf(a3.z, wcol[14], d0); d1 = fmaf(a3.w, wcol[15], d1);
                e0 = fmaf(c3.z, wcol[14], e0); e1 = fmaf(c3.w, wcol[15], e1);
                float h2a = fmaxf(d0 + d1 + aggdot, 0.f);
                float h2b = fmaxf(e0 + e1 + aggdot, 0.f);
                vsum += h2a + h2b;
                vsq   = fmaf(h2a, h2a, vsq); vsq = fmaf(h2b, h2b, vsq);
                Mx1 = fmaxf(Mx1, fmaxf(h2a, h2b));
                Mn1 = fminf(Mn1, fminf(h2a, h2b));
            }
            if (r < nm) {
                const float4* ra = (const float4*)&s_h1[w][r][0];
                float4 a0 = ra[0], a1 = ra[1], a2 = ra[2], a3 = ra[3];
                float d0 = fmaf(a0.x, wcol[0], 0.f), d1 = fmaf(a0.y, wcol[1], 0.f);
                d0 = fmaf(a0.z, wcol[2],  d0); d1 = fmaf(a0.w, wcol[3],  d1);
                d0 = fmaf(a1.x, wcol[4],  d0); d1 = fmaf(a1.y, wcol[5],  d1);
                d0 = fmaf(a1.z, wcol[6],  d0); d1 = fmaf(a1.w, wcol[7],  d1);
                d0 = fmaf(a2.x, wcol[8],  d0); d1 = fmaf(a2.y, wcol[9],  d1);
                d0 = fmaf(a2.z, wcol[10], d0); d1 = fmaf(a2.w, wcol[11], d1);
                d0 = fmaf(a3.x, wcol[12], d0); d1 = fmaf(a3.y, wcol[13], d1);
                d0 = fmaf(a3.z, wcol[14], d0); d1 = fmaf(a3.w, wcol[15], d1);
                float h2a = fmaxf(d0 + d1 + aggdot, 0.f);
                vsum += h2a;
                vsq   = fmaf(h2a, h2a, vsq);
                Mx1 = fmaxf(Mx1, h2a);
                Mn1 = fminf(Mn1, h2a);
            }
            Mx = fmaxf(Mx, Mx1);
            Mn = fminf(Mn, Mn1);

            float* gv = g_vox + (size_t)v * (4 * U2);
            gv[lane]          = Mx;
            gv[U2 + lane]     = Mn;
            gv[2 * U2 + lane] = Mx1;
            gv[3 * U2 + lane] = Mn1;
            if (lane == 0) g_flags[v] = ((nm > 0) ? 1 : 0) | ((nm == T_PTS) ? 2 : 0);
        }
        atomicAdd(&g_sum2[lane], vsum);
        atomicAdd(&g_sq2 [lane], vsq);

        // done with voxels -> help zero
        zero_chunks(o4, n4, lane);
    }

    // ============ join: all warps, all blocks ============
    __syncthreads();
    if (tid == 0) {
        __threadfence();
        atomicAdd(&g_bar2, 1u);
        while (*((volatile unsigned*)&g_bar2) < NBLK) { }
        __threadfence();
    }
    __syncthreads();

    // ============ stage 3: finalize BN2 + scatter ============
    if (tid < U2) {
        float mean = __ldcg(&g_sum2[tid]) * invN;
        float var  = __ldcg(&g_sq2 [tid]) * invN - mean * mean;
        float sc   = rsqrtf(var + EPSBN) * g2[tid];
        s_sc2[tid] = sc;
        s_sh2[tid] = be2[tid] - mean * sc;
    }
    __syncthreads();

    {
        const float sc = s_sc2[lane];
        const float sh = s_sh2[lane];
        for (int v = bid * 8 + w; v < K_VOX; v += NBLK * 8) {
            const float* gv = g_vox + (size_t)v * (4 * U2);
            float Mx  = __ldcg(gv + lane);
            float Mn  = __ldcg(gv + U2 + lane);
            float Mx1 = __ldcg(gv + 2 * U2 + lane);
            float Mn1 = __ldcg(gv + 3 * U2 + lane);
            int   fl  = g_flags[v];
            bool anyM = (fl & 1) != 0;
            bool allM = (fl & 2) != 0;

            float agg2 = fmaf((sc >= 0.f) ? Mx  : Mn,  sc, sh);
            float mskd = fmaf((sc >= 0.f) ? Mx1 : Mn1, sc, sh);

            float vwlo = anyM ? mskd : -INFINITY;
            float vwhi = anyM ? agg2 : -INFINITY;
            if (!allM) { vwlo = fmaxf(vwlo, 0.f); vwhi = fmaxf(vwhi, 0.f); }

            const int* cp = coord + (size_t)v * 4;
            size_t base = ((((size_t)cp[0] * DD + cp[1]) * HH + cp[2]) * WW + cp[3]) * (size_t)(2 * U2);
            atomicAdd(out + base + lane,      vwlo);
            atomicAdd(out + base + U2 + lane, vwhi);
        }
    }
}

// ---------------- launch ----------------
extern "C" void kernel_launch(void* const* d_in, const int* in_sizes, int n_in,
                              void* d_out, int out_size) {
    const float* feat  = (const float*)d_in[0];
    const float* w1    = (const float*)d_in[1];
    const float* b1    = (const float*)d_in[2];
    const float* g1    = (const float*)d_in[3];
    const float* be1   = (const float*)d_in[4];
    const float* w2    = (const float*)d_in[5];
    const float* b2    = (const float*)d_in[6];
    const float* g2    = (const float*)d_in[7];
    const float* be2   = (const float*)d_in[8];
    const int*   coord = (const int*)  d_in[9];
    float* out = (float*)d_out;

    reset_kernel<<<1, 64>>>();
    fused_kernel<<<NBLK, BTHR>>>(feat, w1, b1, g1, be1,
                                 w2, b2, g2, be2, coord, out, out_size);
}

// round 5
// speedup vs baseline: 1.2192x; 1.1969x over previous
#include <cuda_runtime.h>
#include <math.h>

#define K_VOX 40000
#define T_PTS 35
#define C_IN  7
#define U1    16
#define U2    32
#define DD    10
#define HH    400
#define WW    352
#define NROWS (K_VOX * T_PTS)
#define EPSBN 1e-5f
#define H1S   20            // h1 row stride (floats)

// ---------------- global scratch (static, allocation-free) ----------------
__device__ float g_sum1[U1], g_sq1[U1];
__device__ float g_sum2[U2], g_sq2[U2];
__device__ float g_vox[(size_t)K_VOX * 4 * U2];  // [v][{Mx,Mn,Mx1,Mn1}][32]
__device__ int   g_flags[K_VOX];                 // bit0 anyM, bit1 allM

// ---------------- host-side fork/join resources (static init, no device mem) ----
namespace {
struct HostCtx {
    cudaStream_t s2;
    cudaEvent_t  ev_fork, ev_join;
    HostCtx() {
        cudaStreamCreateWithFlags(&s2, cudaStreamNonBlocking);
        cudaEventCreateWithFlags(&ev_fork, cudaEventDisableTiming);
        cudaEventCreateWithFlags(&ev_join, cudaEventDisableTiming);
    }
};
HostCtx g_ctx;
}

__global__ void reset_kernel() {
    int t = threadIdx.x;
    if (t < U1) { g_sum1[t] = 0.f; g_sq1[t] = 0.f; }
    if (t < U2) { g_sum2[t] = 0.f; g_sq2[t] = 0.f; }
}

// ---------------- pass 1: BN1 statistics ----------------
__global__ void __launch_bounds__(256)
stats1_kernel(const float* __restrict__ feat,
              const float* __restrict__ w1,
              const float* __restrict__ b1) {
    __shared__ float sw[C_IN * U1];
    __shared__ float sb[U1];
    __shared__ float ssum[U1], ssq[U1];
    int tid = threadIdx.x;
    if (tid < C_IN * U1) sw[tid] = w1[tid];
    if (tid < U1) { sb[tid] = b1[tid]; ssum[tid] = 0.f; ssq[tid] = 0.f; }
    __syncthreads();

    float psum[U1], psq[U1];
#pragma unroll
    for (int u = 0; u < U1; u++) { psum[u] = 0.f; psq[u] = 0.f; }

    for (int r = blockIdx.x * blockDim.x + tid; r < NROWS;
         r += gridDim.x * blockDim.x) {
        const float* fp = feat + (size_t)r * C_IN;
        float f[C_IN];
#pragma unroll
        for (int c = 0; c < C_IN; c++) f[c] = fp[c];
#pragma unroll
        for (int u = 0; u < U1; u++) {
            float a = sb[u];
#pragma unroll
            for (int c = 0; c < C_IN; c++) a = fmaf(f[c], sw[c * U1 + u], a);
            a = fmaxf(a, 0.f);
            psum[u] += a;
            psq [u]  = fmaf(a, a, psq[u]);
        }
    }
#pragma unroll
    for (int u = 0; u < U1; u++) {
#pragma unroll
        for (int o = 16; o > 0; o >>= 1) {
            psum[u] += __shfl_down_sync(0xFFFFFFFFu, psum[u], o);
            psq [u] += __shfl_down_sync(0xFFFFFFFFu, psq [u], o);
        }
        if ((tid & 31) == 0) { atomicAdd(&ssum[u], psum[u]); atomicAdd(&ssq[u], psq[u]); }
    }
    __syncthreads();
    if (tid < U1) {
        atomicAdd(&g_sum1[tid], ssum[tid]);
        atomicAdd(&g_sq1 [tid], ssq [tid]);
    }
}

// ---------------- pass 2: voxel pass (1 warp = 1 voxel) ----------------
#define VW 8   // warps per block
__global__ void __launch_bounds__(VW * 32, 1)
voxel_kernel(const float* __restrict__ feat,
             const float* __restrict__ g1,  const float* __restrict__ be1,
             const float* __restrict__ w1,  const float* __restrict__ b1,
             const float* __restrict__ w2,  const float* __restrict__ b2) {
    __shared__ float sw1[C_IN * U1];
    __shared__ float sb1[U1];
    __shared__ float s_sc1[U1], s_sh1[U1], s_h1z[U1];
    __shared__ float s_h1[VW][T_PTS][H1S];
    __shared__ float s_agg[VW][U1];
    __shared__ float bsum[U2], bsq[U2];

    const int tid  = threadIdx.x;
    const int w    = tid >> 5;
    const int lane = tid & 31;
    const float invN = 1.0f / (float)NROWS;

    if (tid < C_IN * U1) sw1[tid] = w1[tid];
    if (tid < U2) { bsum[tid] = 0.f; bsq[tid] = 0.f; }
    if (tid < U1) {
        sb1[tid] = b1[tid];
        float mean = g_sum1[tid] * invN;
        float var  = g_sq1 [tid] * invN - mean * mean;
        float sc   = rsqrtf(var + EPSBN) * g1[tid];
        s_sc1[tid] = sc;
        float sh   = be1[tid] - mean * sc;
        s_sh1[tid] = sh;
        s_h1z[tid] = fmaf(fmaxf(b1[tid], 0.f), sc, sh);
    }
    __syncthreads();

    float wcol[U2];
#pragma unroll
    for (int i = 0; i < U2; i++) wcol[i] = w2[i * U2 + lane];
    const float b2l = b2[lane];
    const float h2z = fmaxf(b2l, 0.f);

    const int v = blockIdx.x * VW + w;   // grid covers K_VOX exactly
    const float* fv = feat + (size_t)v * T_PTS * C_IN;

    unsigned mb0, mb1;
    {   // rows t = lane
        const float* fp = fv + lane * C_IN;
        float f[C_IN]; float mx = -INFINITY;
#pragma unroll
        for (int c = 0; c < C_IN; c++) { f[c] = fp[c]; mx = fmaxf(mx, f[c]); }
        bool msk = (mx != 0.0f);
        mb0 = __ballot_sync(0xFFFFFFFFu, msk);
        if (msk) {
            int rank = __popc(mb0 & ((1u << lane) - 1u));
            float h[U1];
#pragma unroll
            for (int u = 0; u < U1; u++) {
                float a = sb1[u];
#pragma unroll
                for (int c = 0; c < C_IN; c++) a = fmaf(f[c], sw1[c * U1 + u], a);
                a = fmaxf(a, 0.f);
                h[u] = fmaf(a, s_sc1[u], s_sh1[u]);
            }
            float4* row = (float4*)&s_h1[w][rank][0];
            row[0] = make_float4(h[0],  h[1],  h[2],  h[3]);
            row[1] = make_float4(h[4],  h[5],  h[6],  h[7]);
            row[2] = make_float4(h[8],  h[9],  h[10], h[11]);
            row[3] = make_float4(h[12], h[13], h[14], h[15]);
        }
    }
    {   // rows t = 32 + lane (3 valid)
        bool act = (lane < (T_PTS - 32));
        float f[C_IN]; float mx = -INFINITY;
        if (act) {
            const float* fp = fv + (32 + lane) * C_IN;
#pragma unroll
            for (int c = 0; c < C_IN; c++) { f[c] = fp[c]; mx = fmaxf(mx, f[c]); }
        }
        bool msk = act && (mx != 0.0f);
        mb1 = __ballot_sync(0xFFFFFFFFu, msk);
        if (msk) {
            int rank = __popc(mb0) + __popc(mb1 & ((1u << lane) - 1u));
            float h[U1];
#pragma unroll
            for (int u = 0; u < U1; u++) {
                float a = sb1[u];
#pragma unroll
                for (int c = 0; c < C_IN; c++) a = fmaf(f[c], sw1[c * U1 + u], a);
                a = fmaxf(a, 0.f);
                h[u] = fmaf(a, s_sc1[u], s_sh1[u]);
            }
            float4* row = (float4*)&s_h1[w][rank][0];
            row[0] = make_float4(h[0],  h[1],  h[2],  h[3]);
            row[1] = make_float4(h[4],  h[5],  h[6],  h[7]);
            row[2] = make_float4(h[8],  h[9],  h[10], h[11]);
            row[3] = make_float4(h[12], h[13], h[14], h[15]);
        }
    }
    const int nm = __popc(mb0) + __popc(mb1);
    const int nz = T_PTS - nm;
    __syncwarp();

    if (lane < U1) {
        float mx = (nz > 0) ? s_h1z[lane] : -INFINITY;
        for (int r = 0; r < nm; r++) mx = fmaxf(mx, s_h1[w][r][lane]);
        s_agg[w][lane] = mx;
    }
    __syncwarp();

    float aggdot = b2l;   // fold bias in
#pragma unroll
    for (int j = 0; j < U1; j++)
        aggdot = fmaf(s_agg[w][j], wcol[U1 + j], aggdot);

    float vsum = 0.f, vsq = 0.f;
    float Mx1 = -INFINITY, Mn1 = INFINITY;
    {
        float fz = (float)nz;
        vsum += fz * h2z;
        vsq   = fmaf(fz, h2z * h2z, vsq);
    }

    int r = 0;
    for (; r + 2 <= nm; r += 2) {
        const float4* ra = (const float4*)&s_h1[w][r][0];
        const float4* rb = (const float4*)&s_h1[w][r + 1][0];
        float4 a0 = ra[0], a1 = ra[1], a2 = ra[2], a3 = ra[3];
        float4 c0 = rb[0], c1 = rb[1], c2 = rb[2], c3 = rb[3];
        float d0 = a0.x * wcol[0], d1 = a0.y * wcol[1];
        float e0 = c0.x * wcol[0], e1 = c0.y * wcol[1];
        d0 = fmaf(a0.z, wcol[2],  d0); d1 = fmaf(a0.w, wcol[3],  d1);
        e0 = fmaf(c0.z, wcol[2],  e0); e1 = fmaf(c0.w, wcol[3],  e1);
        d0 = fmaf(a1.x, wcol[4],  d0); d1 = fmaf(a1.y, wcol[5],  d1);
        e0 = fmaf(c1.x, wcol[4],  e0); e1 = fmaf(c1.y, wcol[5],  e1);
        d0 = fmaf(a1.z, wcol[6],  d0); d1 = fmaf(a1.w, wcol[7],  d1);
        e0 = fmaf(c1.z, wcol[6],  e0); e1 = fmaf(c1.w, wcol[7],  e1);
        d0 = fmaf(a2.x, wcol[8],  d0); d1 = fmaf(a2.y, wcol[9],  d1);
        e0 = fmaf(c2.x, wcol[8],  e0); e1 = fmaf(c2.y, wcol[9],  e1);
        d0 = fmaf(a2.z, wcol[10], d0); d1 = fmaf(a2.w, wcol[11], d1);
        e0 = fmaf(c2.z, wcol[10], e0); e1 = fmaf(c2.w, wcol[11], e1);
        d0 = fmaf(a3.x, wcol[12], d0); d1 = fmaf(a3.y, wcol[13], d1);
        e0 = fmaf(c3.x, wcol[12], e0); e1 = fmaf(c3.y, wcol[13], e1);
        d0 = fmaf(a3.z, wcol[14], d0); d1 = fmaf(a3.w, wcol[15], d1);
        e0 = fmaf(c3.z, wcol[14], e0); e1 = fmaf(c3.w, wcol[15], e1);
        float h2a = fmaxf(d0 + d1 + aggdot, 0.f);
        float h2b = fmaxf(e0 + e1 + aggdot, 0.f);
        vsum += h2a + h2b;
        vsq   = fmaf(h2a, h2a, vsq); vsq = fmaf(h2b, h2b, vsq);
        Mx1 = fmaxf(Mx1, fmaxf(h2a, h2b));
        Mn1 = fminf(Mn1, fminf(h2a, h2b));
    }
    if (r < nm) {
        const float4* ra = (const float4*)&s_h1[w][r][0];
        float4 a0 = ra[0], a1 = ra[1], a2 = ra[2], a3 = ra[3];
        float d0 = a0.x * wcol[0], d1 = a0.y * wcol[1];
        d0 = fmaf(a0.z, wcol[2],  d0); d1 = fmaf(a0.w, wcol[3],  d1);
        d0 = fmaf(a1.x, wcol[4],  d0); d1 = fmaf(a1.y, wcol[5],  d1);
        d0 = fmaf(a1.z, wcol[6],  d0); d1 = fmaf(a1.w, wcol[7],  d1);
        d0 = fmaf(a2.x, wcol[8],  d0); d1 = fmaf(a2.y, wcol[9],  d1);
        d0 = fmaf(a2.z, wcol[10], d0); d1 = fmaf(a2.w, wcol[11], d1);
        d0 = fmaf(a3.x, wcol[12], d0); d1 = fmaf(a3.y, wcol[13], d1);
        d0 = fmaf(a3.z, wcol[14], d0); d1 = fmaf(a3.w, wcol[15], d1);
        float h2a = fmaxf(d0 + d1 + aggdot, 0.f);
        vsum += h2a;
        vsq   = fmaf(h2a, h2a, vsq);
        Mx1 = fmaxf(Mx1, h2a);
        Mn1 = fminf(Mn1, h2a);
    }
    float Mx = (nz > 0) ? fmaxf(Mx1, h2z) : Mx1;
    float Mn = (nz > 0) ? fminf(Mn1, h2z) : Mn1;

    float* gv = g_vox + (size_t)v * (4 * U2);
    gv[lane]          = Mx;
    gv[U2 + lane]     = Mn;
    gv[2 * U2 + lane] = Mx1;
    gv[3 * U2 + lane] = Mn1;
    if (lane == 0) g_flags[v] = ((nm > 0) ? 1 : 0) | ((nm == T_PTS) ? 2 : 0);

    // block-level BN2 stat reduction, then one atomic per channel per block
    atomicAdd(&bsum[lane], vsum);
    atomicAdd(&bsq [lane], vsq);
    __syncthreads();
    if (tid < U2) {
        atomicAdd(&g_sum2[tid], bsum[tid]);
        atomicAdd(&g_sq2 [tid], bsq [tid]);
    }
}

// ---------------- pass 3: finalize BN2 + scatter ----------------
__global__ void __launch_bounds__(256)
scatter_kernel(const float* __restrict__ g2, const float* __restrict__ be2,
               const int* __restrict__ coord, float* __restrict__ out) {
    __shared__ float s_sc2[U2], s_sh2[U2];
    const int tid  = threadIdx.x;
    const int w    = tid >> 5;
    const int lane = tid & 31;
    const float invN = 1.0f / (float)NROWS;

    if (tid < U2) {
        float mean = g_sum2[tid] * invN;
        float var  = g_sq2 [tid] * invN - mean * mean;
        float sc   = rsqrtf(var + EPSBN) * g2[tid];
        s_sc2[tid] = sc;
        s_sh2[tid] = be2[tid] - mean * sc;
    }
    __syncthreads();

    const float sc = s_sc2[lane];
    const float sh = s_sh2[lane];
    const int v = blockIdx.x * 8 + w;   // grid covers K_VOX exactly

    const float* gv = g_vox + (size_t)v * (4 * U2);
    float Mx  = __ldcg(gv + lane);
    float Mn  = __ldcg(gv + U2 + lane);
    float Mx1 = __ldcg(gv + 2 * U2 + lane);
    float Mn1 = __ldcg(gv + 3 * U2 + lane);
    int   fl  = g_flags[v];
    bool anyM = (fl & 1) != 0;
    bool allM = (fl & 2) != 0;

    float agg2 = fmaf((sc >= 0.f) ? Mx  : Mn,  sc, sh);
    float mskd = fmaf((sc >= 0.f) ? Mx1 : Mn1, sc, sh);

    float vwlo = anyM ? mskd : -INFINITY;
    float vwhi = anyM ? agg2 : -INFINITY;
    if (!allM) { vwlo = fmaxf(vwlo, 0.f); vwhi = fmaxf(vwhi, 0.f); }

    const int* cp = coord + (size_t)v * 4;
    size_t base = ((((size_t)cp[0] * DD + cp[1]) * HH + cp[2]) * WW + cp[3]) * (size_t)(2 * U2);
    atomicAdd(out + base + lane,      vwlo);
    atomicAdd(out + base + U2 + lane, vwhi);
}

// ---------------- launch ----------------
extern "C" void kernel_launch(void* const* d_in, const int* in_sizes, int n_in,
                              void* d_out, int out_size) {
    const float* feat  = (const float*)d_in[0];
    const float* w1    = (const float*)d_in[1];
    const float* b1    = (const float*)d_in[2];
    const float* g1    = (const float*)d_in[3];
    const float* be1   = (const float*)d_in[4];
    const float* w2    = (const float*)d_in[5];
    const float* b2    = (const float*)d_in[6];
    const float* g2    = (const float*)d_in[7];
    const float* be2   = (const float*)d_in[8];
    const int*   coord = (const int*)  d_in[9];
    float* out = (float*)d_out;

    // fork: driver memset (fast path, ~6 TB/s) runs on s2 concurrently
    cudaEventRecord(g_ctx.ev_fork, 0);
    cudaStreamWaitEvent(g_ctx.s2, g_ctx.ev_fork, 0);
    cudaMemsetAsync(d_out, 0, (size_t)out_size * sizeof(float), g_ctx.s2);
    cudaEventRecord(g_ctx.ev_join, g_ctx.s2);

    // compute chain on the captured stream
    reset_kernel<<<1, 64>>>();
    stats1_kernel<<<1184, 256>>>(feat, w1, b1);
    voxel_kernel<<<K_VOX / VW, VW * 32>>>(feat, g1, be1, w1, b1, w2, b2);

    // join: scatter needs both the zeroed grid and the voxel results
    cudaStreamWaitEvent(0, g_ctx.ev_join, 0);
    scatter_kernel<<<K_VOX / 8, 256>>>(g2, be2, coord, out);
}

// round 6
// speedup vs baseline: 1.2240x; 1.0040x over previous
#include <cuda_runtime.h>
#include <math.h>

#define K_VOX 40000
#define T_PTS 35
#define C_IN  7
#define U1    16
#define U2    32
#define DD    10
#define HH    400
#define WW    352
#define NROWS (K_VOX * T_PTS)
#define EPSBN 1e-5f
#define H1S   20            // h1 row stride (floats)

// ---------------- global scratch (static, allocation-free) ----------------
__device__ float g_sum1[U1], g_sq1[U1];
__device__ float g_sum2[U2], g_sq2[U2];
__device__ float g_vox[(size_t)K_VOX * 4 * U2];  // [v][{Mx,Mn,Mx1,Mn1}][32]
__device__ int   g_flags[K_VOX];                 // bit0 anyM, bit1 allM

// ---------------- host-side fork/join resources (static init, no device mem) ----
namespace {
struct HostCtx {
    cudaStream_t s2;
    cudaEvent_t  ev_fork, ev_join;
    HostCtx() {
        cudaStreamCreateWithFlags(&s2, cudaStreamNonBlocking);
        cudaEventCreateWithFlags(&ev_fork, cudaEventDisableTiming);
        cudaEventCreateWithFlags(&ev_join, cudaEventDisableTiming);
    }
};
HostCtx g_ctx;
}

__global__ void reset_kernel() {
    int t = threadIdx.x;
    if (t < U1) { g_sum1[t] = 0.f; g_sq1[t] = 0.f; }
    if (t < U2) { g_sum2[t] = 0.f; g_sq2[t] = 0.f; }
}

// ---------------- pass 1: BN1 statistics ----------------
__global__ void __launch_bounds__(256)
stats1_kernel(const float* __restrict__ feat,
              const float* __restrict__ w1,
              const float* __restrict__ b1) {
    __shared__ float sw[C_IN * U1];
    __shared__ float sb[U1];
    __shared__ float ssum[U1], ssq[U1];
    int tid = threadIdx.x;
    if (tid < C_IN * U1) sw[tid] = w1[tid];
    if (tid < U1) { sb[tid] = b1[tid]; ssum[tid] = 0.f; ssq[tid] = 0.f; }
    __syncthreads();

    float psum[U1], psq[U1];
#pragma unroll
    for (int u = 0; u < U1; u++) { psum[u] = 0.f; psq[u] = 0.f; }

    for (int r = blockIdx.x * blockDim.x + tid; r < NROWS;
         r += gridDim.x * blockDim.x) {
        const float* fp = feat + (size_t)r * C_IN;
        float f[C_IN];
#pragma unroll
        for (int c = 0; c < C_IN; c++) f[c] = fp[c];
#pragma unroll
        for (int u = 0; u < U1; u++) {
            float a = sb[u];
#pragma unroll
            for (int c = 0; c < C_IN; c++) a = fmaf(f[c], sw[c * U1 + u], a);
            a = fmaxf(a, 0.f);
            psum[u] += a;
            psq [u]  = fmaf(a, a, psq[u]);
        }
    }
#pragma unroll
    for (int u = 0; u < U1; u++) {
#pragma unroll
        for (int o = 16; o > 0; o >>= 1) {
            psum[u] += __shfl_down_sync(0xFFFFFFFFu, psum[u], o);
            psq [u] += __shfl_down_sync(0xFFFFFFFFu, psq [u], o);
        }
        if ((tid & 31) == 0) { atomicAdd(&ssum[u], psum[u]); atomicAdd(&ssq[u], psq[u]); }
    }
    __syncthreads();
    if (tid < U1) {
        atomicAdd(&g_sum1[tid], ssum[tid]);
        atomicAdd(&g_sq1 [tid], ssq [tid]);
    }
}

// ---------------- pass 2: voxel pass (1 warp = 1 voxel) ----------------
#define VW 8   // warps per block
__global__ void __launch_bounds__(VW * 32, 2)    // cap 128 regs -> 2 blocks/SM
voxel_kernel(const float* __restrict__ feat,
             const float* __restrict__ g1,  const float* __restrict__ be1,
             const float* __restrict__ w1,  const float* __restrict__ b1,
             const float* __restrict__ w2,  const float* __restrict__ b2) {
    __shared__ float sw1[C_IN * U1];
    __shared__ float sb1[U1];
    __shared__ float s_sc1[U1], s_sh1[U1], s_h1z[U1];
    __shared__ float s_h1[VW][T_PTS][H1S];
    __shared__ float s_agg[VW][U1];
    __shared__ float bsum[U2], bsq[U2];

    const int tid  = threadIdx.x;
    const int w    = tid >> 5;
    const int lane = tid & 31;
    const float invN = 1.0f / (float)NROWS;

    if (tid < C_IN * U1) sw1[tid] = w1[tid];
    if (tid < U2) { bsum[tid] = 0.f; bsq[tid] = 0.f; }
    if (tid < U1) {
        sb1[tid] = b1[tid];
        float mean = g_sum1[tid] * invN;
        float var  = g_sq1 [tid] * invN - mean * mean;
        float sc   = rsqrtf(var + EPSBN) * g1[tid];
        s_sc1[tid] = sc;
        float sh   = be1[tid] - mean * sc;
        s_sh1[tid] = sh;
        s_h1z[tid] = fmaf(fmaxf(b1[tid], 0.f), sc, sh);
    }
    __syncthreads();

    const float b2l = b2[lane];
    const float h2z = fmaxf(b2l, 0.f);

    const int v = blockIdx.x * VW + w;   // grid covers K_VOX exactly
    const float* fv = feat + (size_t)v * T_PTS * C_IN;

    unsigned mb0, mb1;
    {   // rows t = lane
        const float* fp = fv + lane * C_IN;
        float f[C_IN]; float mx = -INFINITY;
#pragma unroll
        for (int c = 0; c < C_IN; c++) { f[c] = fp[c]; mx = fmaxf(mx, f[c]); }
        bool msk = (mx != 0.0f);
        mb0 = __ballot_sync(0xFFFFFFFFu, msk);
        if (msk) {
            int rank = __popc(mb0 & ((1u << lane) - 1u));
            float h[U1];
#pragma unroll
            for (int u = 0; u < U1; u++) {
                float a = sb1[u];
#pragma unroll
                for (int c = 0; c < C_IN; c++) a = fmaf(f[c], sw1[c * U1 + u], a);
                a = fmaxf(a, 0.f);
                h[u] = fmaf(a, s_sc1[u], s_sh1[u]);
            }
            float4* row = (float4*)&s_h1[w][rank][0];
            row[0] = make_float4(h[0],  h[1],  h[2],  h[3]);
            row[1] = make_float4(h[4],  h[5],  h[6],  h[7]);
            row[2] = make_float4(h[8],  h[9],  h[10], h[11]);
            row[3] = make_float4(h[12], h[13], h[14], h[15]);
        }
    }
    {   // rows t = 32 + lane (3 valid)
        bool act = (lane < (T_PTS - 32));
        float f[C_IN]; float mx = -INFINITY;
        if (act) {
            const float* fp = fv + (32 + lane) * C_IN;
#pragma unroll
            for (int c = 0; c < C_IN; c++) { f[c] = fp[c]; mx = fmaxf(mx, f[c]); }
        }
        bool msk = act && (mx != 0.0f);
        mb1 = __ballot_sync(0xFFFFFFFFu, msk);
        if (msk) {
            int rank = __popc(mb0) + __popc(mb1 & ((1u << lane) - 1u));
            float h[U1];
#pragma unroll
            for (int u = 0; u < U1; u++) {
                float a = sb1[u];
#pragma unroll
                for (int c = 0; c < C_IN; c++) a = fmaf(f[c], sw1[c * U1 + u], a);
                a = fmaxf(a, 0.f);
                h[u] = fmaf(a, s_sc1[u], s_sh1[u]);
            }
            float4* row = (float4*)&s_h1[w][rank][0];
            row[0] = make_float4(h[0],  h[1],  h[2],  h[3]);
            row[1] = make_float4(h[4],  h[5],  h[6],  h[7]);
            row[2] = make_float4(h[8],  h[9],  h[10], h[11]);
            row[3] = make_float4(h[12], h[13], h[14], h[15]);
        }
    }
    const int nm = __popc(mb0) + __popc(mb1);
    const int nz = T_PTS - nm;
    __syncwarp();

    if (lane < U1) {
        float mx = (nz > 0) ? s_h1z[lane] : -INFINITY;
        for (int r = 0; r < nm; r++) mx = fmaxf(mx, s_h1[w][r][lane]);
        s_agg[w][lane] = mx;
    }
    __syncwarp();

    // aggdot uses w2 rows 16..31 transiently (no long-lived registers)
    float aggdot = b2l;
    {
#pragma unroll
        for (int j = 0; j < U1; j++)
            aggdot = fmaf(s_agg[w][j], __ldg(&w2[(U1 + j) * U2 + lane]), aggdot);
    }

    // only the inner-dot half of w2 stays resident
    float wcol[U1];
#pragma unroll
    for (int i = 0; i < U1; i++) wcol[i] = w2[i * U2 + lane];

    float vsum = 0.f, vsq = 0.f;
    float Mx1 = -INFINITY, Mn1 = INFINITY;
    {
        float fz = (float)nz;
        vsum += fz * h2z;
        vsq   = fmaf(fz, h2z * h2z, vsq);
    }

    int r = 0;
    for (; r + 2 <= nm; r += 2) {
        const float4* ra = (const float4*)&s_h1[w][r][0];
        const float4* rb = (const float4*)&s_h1[w][r + 1][0];
        float4 a0 = ra[0], a1 = ra[1], a2 = ra[2], a3 = ra[3];
        float4 c0 = rb[0], c1 = rb[1], c2 = rb[2], c3 = rb[3];
        float d0 = a0.x * wcol[0], d1 = a0.y * wcol[1];
        float e0 = c0.x * wcol[0], e1 = c0.y * wcol[1];
        d0 = fmaf(a0.z, wcol[2],  d0); d1 = fmaf(a0.w, wcol[3],  d1);
        e0 = fmaf(c0.z, wcol[2],  e0); e1 = fmaf(c0.w, wcol[3],  e1);
        d0 = fmaf(a1.x, wcol[4],  d0); d1 = fmaf(a1.y, wcol[5],  d1);
        e0 = fmaf(c1.x, wcol[4],  e0); e1 = fmaf(c1.y, wcol[5],  e1);
        d0 = fmaf(a1.z, wcol[6],  d0); d1 = fmaf(a1.w, wcol[7],  d1);
        e0 = fmaf(c1.z, wcol[6],  e0); e1 = fmaf(c1.w, wcol[7],  e1);
        d0 = fmaf(a2.x, wcol[8],  d0); d1 = fmaf(a2.y, wcol[9],  d1);
        e0 = fmaf(c2.x, wcol[8],  e0); e1 = fmaf(c2.y, wcol[9],  e1);
        d0 = fmaf(a2.z, wcol[10], d0); d1 = fmaf(a2.w, wcol[11], d1);
        e0 = fmaf(c2.z, wcol[10], e0); e1 = fmaf(c2.w, wcol[11], e1);
        d0 = fmaf(a3.x, wcol[12], d0); d1 = fmaf(a3.y, wcol[13], d1);
        e0 = fmaf(c3.x, wcol[12], e0); e1 = fmaf(c3.y, wcol[13], e1);
        d0 = fmaf(a3.z, wcol[14], d0); d1 = fmaf(a3.w, wcol[15], d1);
        e0 = fmaf(c3.z, wcol[14], e0); e1 = fmaf(c3.w, wcol[15], e1);
        float h2a = fmaxf(d0 + d1 + aggdot, 0.f);
        float h2b = fmaxf(e0 + e1 + aggdot, 0.f);
        vsum += h2a + h2b;
        vsq   = fmaf(h2a, h2a, vsq); vsq = fmaf(h2b, h2b, vsq);
        Mx1 = fmaxf(Mx1, fmaxf(h2a, h2b));
        Mn1 = fminf(Mn1, fminf(h2a, h2b));
    }
    if (r < nm) {
        const float4* ra = (const float4*)&s_h1[w][r][0];
        float4 a0 = ra[0], a1 = ra[1], a2 = ra[2], a3 = ra[3];
        float d0 = a0.x * wcol[0], d1 = a0.y * wcol[1];
        d0 = fmaf(a0.z, wcol[2],  d0); d1 = fmaf(a0.w, wcol[3],  d1);
        d0 = fmaf(a1.x, wcol[4],  d0); d1 = fmaf(a1.y, wcol[5],  d1);
        d0 = fmaf(a1.z, wcol[6],  d0); d1 = fmaf(a1.w, wcol[7],  d1);
        d0 = fmaf(a2.x, wcol[8],  d0); d1 = fmaf(a2.y, wcol[9],  d1);
        d0 = fmaf(a2.z, wcol[10], d0); d1 = fmaf(a2.w, wcol[11], d1);
        d0 = fmaf(a3.x, wcol[12], d0); d1 = fmaf(a3.y, wcol[13], d1);
        d0 = fmaf(a3.z, wcol[14], d0); d1 = fmaf(a3.w, wcol[15], d1);
        float h2a = fmaxf(d0 + d1 + aggdot, 0.f);
        vsum += h2a;
        vsq   = fmaf(h2a, h2a, vsq);
        Mx1 = fmaxf(Mx1, h2a);
        Mn1 = fminf(Mn1, h2a);
    }
    float Mx = (nz > 0) ? fmaxf(Mx1, h2z) : Mx1;
    float Mn = (nz > 0) ? fminf(Mn1, h2z) : Mn1;

    float* gv = g_vox + (size_t)v * (4 * U2);
    gv[lane]          = Mx;
    gv[U2 + lane]     = Mn;
    gv[2 * U2 + lane] = Mx1;
    gv[3 * U2 + lane] = Mn1;
    if (lane == 0) g_flags[v] = ((nm > 0) ? 1 : 0) | ((nm == T_PTS) ? 2 : 0);

    // block-level BN2 stat reduction, then one atomic per channel per block
    atomicAdd(&bsum[lane], vsum);
    atomicAdd(&bsq [lane], vsq);
    __syncthreads();
    if (tid < U2) {
        atomicAdd(&g_sum2[tid], bsum[tid]);
        atomicAdd(&g_sq2 [tid], bsq [tid]);
    }
}

// ---------------- pass 3: finalize BN2 + scatter ----------------
__global__ void __launch_bounds__(256)
scatter_kernel(const float* __restrict__ g2, const float* __restrict__ be2,
               const int* __restrict__ coord, float* __restrict__ out) {
    __shared__ float s_sc2[U2], s_sh2[U2];
    const int tid  = threadIdx.x;
    const int w    = tid >> 5;
    const int lane = tid & 31;
    const float invN = 1.0f / (float)NROWS;

    if (tid < U2) {
        float mean = g_sum2[tid] * invN;
        float var  = g_sq2 [tid] * invN - mean * mean;
        float sc   = rsqrtf(var + EPSBN) * g2[tid];
        s_sc2[tid] = sc;
        s_sh2[tid] = be2[tid] - mean * sc;
    }
    __syncthreads();

    const float sc = s_sc2[lane];
    const float sh = s_sh2[lane];
    const int v = blockIdx.x * 8 + w;   // grid covers K_VOX exactly

    const float* gv = g_vox + (size_t)v * (4 * U2);
    float Mx  = __ldcg(gv + lane);
    float Mn  = __ldcg(gv + U2 + lane);
    float Mx1 = __ldcg(gv + 2 * U2 + lane);
    float Mn1 = __ldcg(gv + 3 * U2 + lane);
    int   fl  = g_flags[v];
    bool anyM = (fl & 1) != 0;
    bool allM = (fl & 2) != 0;

    float agg2 = fmaf((sc >= 0.f) ? Mx  : Mn,  sc, sh);
    float mskd = fmaf((sc >= 0.f) ? Mx1 : Mn1, sc, sh);

    float vwlo = anyM ? mskd : -INFINITY;
    float vwhi = anyM ? agg2 : -INFINITY;
    if (!allM) { vwlo = fmaxf(vwlo, 0.f); vwhi = fmaxf(vwhi, 0.f); }

    const int* cp = coord + (size_t)v * 4;
    size_t base = ((((size_t)cp[0] * DD + cp[1]) * HH + cp[2]) * WW + cp[3]) * (size_t)(2 * U2);
    atomicAdd(out + base + lane,      vwlo);
    atomicAdd(out + base + U2 + lane, vwhi);
}

// ---------------- launch ----------------
extern "C" void kernel_launch(void* const* d_in, const int* in_sizes, int n_in,
                              void* d_out, int out_size) {
    const float* feat  = (const float*)d_in[0];
    const float* w1    = (const float*)d_in[1];
    const float* b1    = (const float*)d_in[2];
    const float* g1    = (const float*)d_in[3];
    const float* be1   = (const float*)d_in[4];
    const float* w2    = (const float*)d_in[5];
    const float* b2    = (const float*)d_in[6];
    const float* g2    = (const float*)d_in[7];
    const float* be2   = (const float*)d_in[8];
    const int*   coord = (const int*)  d_in[9];
    float* out = (float*)d_out;

    // fork: driver memset (fast path) runs on s2 concurrently with compute
    cudaEventRecord(g_ctx.ev_fork, 0);
    cudaStreamWaitEvent(g_ctx.s2, g_ctx.ev_fork, 0);
    cudaMemsetAsync(d_out, 0, (size_t)out_size * sizeof(float), g_ctx.s2);
    cudaEventRecord(g_ctx.ev_join, g_ctx.s2);

    // compute chain on the captured stream
    reset_kernel<<<1, 64>>>();
    stats1_kernel<<<1184, 256>>>(feat, w1, b1);
    voxel_kernel<<<K_VOX / VW, VW * 32>>>(feat, g1, be1, w1, b1, w2, b2);

    // join: scatter needs both the zeroed grid and the voxel results
    cudaStreamWaitEvent(0, g_ctx.ev_join, 0);
    scatter_kernel<<<K_VOX / 8, 256>>>(g2, be2, coord, out);
}

// round 7
// speedup vs baseline: 1.3599x; 1.1110x over previous
#include <cuda_runtime.h>
#include <math.h>

#define K_VOX 40000
#define T_PTS 35
#define C_IN  7
#define U1    16
#define U2    32
#define DD    10
#define HH    400
#define WW    352
#define NROWS (K_VOX * T_PTS)
#define EPSBN 1e-5f
#define H1S   20            // h1 row stride (floats)

#define NBLK  148           // persistent blocks, 1 per SM
#define VW    8             // warps per block

// ---------------- global scratch (static, allocation-free) ----------------
__device__ float    g_sum1[U1], g_sq1[U1];
__device__ float    g_sum2[U2], g_sq2[U2];
__device__ unsigned g_bar1;
__device__ float    g_vox[(size_t)K_VOX * 4 * U2];  // [v][{Mx,Mn,Mx1,Mn1}][32]
__device__ int      g_flags[K_VOX];                 // bit0 anyM, bit1 allM

// ---------------- host-side fork/join resources (static init, no device mem) ----
namespace {
struct HostCtx {
    cudaStream_t s2;
    cudaEvent_t  ev_fork, ev_join;
    HostCtx() {
        cudaStreamCreateWithFlags(&s2, cudaStreamNonBlocking);
        cudaEventCreateWithFlags(&ev_fork, cudaEventDisableTiming);
        cudaEventCreateWithFlags(&ev_join, cudaEventDisableTiming);
    }
};
HostCtx g_ctx;
}

__global__ void reset_kernel() {
    int t = threadIdx.x;
    if (t < U1) { g_sum1[t] = 0.f; g_sq1[t] = 0.f; }
    if (t < U2) { g_sum2[t] = 0.f; g_sq2[t] = 0.f; }
    if (t == 0) g_bar1 = 0u;
}

// grid barrier: all NBLK blocks resident by construction (1 block/SM)
__device__ __forceinline__ void gsync() {
    __syncthreads();
    if (threadIdx.x == 0) {
        __threadfence();
        atomicAdd(&g_bar1, 1u);
        while (*((volatile unsigned*)&g_bar1) < NBLK) { }
        __threadfence();
    }
    __syncthreads();
}

// ---------------- persistent compute: BN1 stats + voxel pass ----------------
__global__ void __launch_bounds__(VW * 32, 1)
compute_kernel(const float* __restrict__ feat,
               const float* __restrict__ g1,  const float* __restrict__ be1,
               const float* __restrict__ w1,  const float* __restrict__ b1,
               const float* __restrict__ w2,  const float* __restrict__ b2) {
    __shared__ float sw1[C_IN * U1];
    __shared__ float sb1[U1];
    __shared__ float s_sc1[U1], s_sh1[U1], s_h1z[U1];
    __shared__ float ssum[U1], ssq[U1];
    __shared__ float s_h1[VW][T_PTS][H1S];
    __shared__ float s_agg[VW][U1];
    __shared__ float bsum[U2], bsq[U2];

    const int tid  = threadIdx.x;
    const int w    = tid >> 5;
    const int lane = tid & 31;
    const int bid  = blockIdx.x;
    const float invN = 1.0f / (float)NROWS;

    if (tid < C_IN * U1) sw1[tid] = w1[tid];
    if (tid < U2) { bsum[tid] = 0.f; bsq[tid] = 0.f; }
    if (tid < U1) { sb1[tid] = b1[tid]; ssum[tid] = 0.f; ssq[tid] = 0.f; }
    __syncthreads();

    // ===== stage 1: BN1 statistics =====
    {
        float psum[U1], psq[U1];
#pragma unroll
        for (int u = 0; u < U1; u++) { psum[u] = 0.f; psq[u] = 0.f; }
        for (int r = bid * (VW * 32) + tid; r < NROWS; r += NBLK * (VW * 32)) {
            const float* fp = feat + (size_t)r * C_IN;
            float f[C_IN];
#pragma unroll
            for (int c = 0; c < C_IN; c++) f[c] = fp[c];
#pragma unroll
            for (int u = 0; u < U1; u++) {
                float a = sb1[u];
#pragma unroll
                for (int c = 0; c < C_IN; c++) a = fmaf(f[c], sw1[c * U1 + u], a);
                a = fmaxf(a, 0.f);
                psum[u] += a;
                psq [u]  = fmaf(a, a, psq[u]);
            }
        }
#pragma unroll
        for (int u = 0; u < U1; u++) {
#pragma unroll
            for (int o = 16; o > 0; o >>= 1) {
                psum[u] += __shfl_down_sync(0xFFFFFFFFu, psum[u], o);
                psq [u] += __shfl_down_sync(0xFFFFFFFFu, psq [u], o);
            }
            if (lane == 0) { atomicAdd(&ssum[u], psum[u]); atomicAdd(&ssq[u], psq[u]); }
        }
        __syncthreads();
        if (tid < U1) {
            atomicAdd(&g_sum1[tid], ssum[tid]);
            atomicAdd(&g_sq1 [tid], ssq [tid]);
        }
    }
    gsync();

    // fold BN1 into scale/shift
    if (tid < U1) {
        float mean = __ldcg(&g_sum1[tid]) * invN;
        float var  = __ldcg(&g_sq1 [tid]) * invN - mean * mean;
        float sc   = rsqrtf(var + EPSBN) * g1[tid];
        s_sc1[tid] = sc;
        float sh   = be1[tid] - mean * sc;
        s_sh1[tid] = sh;
        s_h1z[tid] = fmaf(fmaxf(sb1[tid], 0.f), sc, sh);
    }
    __syncthreads();

    // ===== stage 2: voxel loop (1 warp = 1 voxel per iteration) =====
    const float b2l = b2[lane];
    const float h2z = fmaxf(b2l, 0.f);
    float wcol[U1];
#pragma unroll
    for (int i = 0; i < U1; i++) wcol[i] = w2[i * U2 + lane];
    float wagg[U1];
#pragma unroll
    for (int i = 0; i < U1; i++) wagg[i] = w2[(U1 + i) * U2 + lane];

    float vsum = 0.f, vsq = 0.f;

    for (int v = bid * VW + w; v < K_VOX; v += NBLK * VW) {
        const float* fv = feat + (size_t)v * T_PTS * C_IN;

        unsigned mb0, mb1;
        {   // rows t = lane
            const float* fp = fv + lane * C_IN;
            float f[C_IN]; float mx = -INFINITY;
#pragma unroll
            for (int c = 0; c < C_IN; c++) { f[c] = fp[c]; mx = fmaxf(mx, f[c]); }
            bool msk = (mx != 0.0f);
            mb0 = __ballot_sync(0xFFFFFFFFu, msk);
            if (msk) {
                int rank = __popc(mb0 & ((1u << lane) - 1u));
                float h[U1];
#pragma unroll
                for (int u = 0; u < U1; u++) {
                    float a = sb1[u];
#pragma unroll
                    for (int c = 0; c < C_IN; c++) a = fmaf(f[c], sw1[c * U1 + u], a);
                    a = fmaxf(a, 0.f);
                    h[u] = fmaf(a, s_sc1[u], s_sh1[u]);
                }
                float4* row = (float4*)&s_h1[w][rank][0];
                row[0] = make_float4(h[0],  h[1],  h[2],  h[3]);
                row[1] = make_float4(h[4],  h[5],  h[6],  h[7]);
                row[2] = make_float4(h[8],  h[9],  h[10], h[11]);
                row[3] = make_float4(h[12], h[13], h[14], h[15]);
            }
        }
        {   // rows t = 32 + lane (3 valid)
            bool act = (lane < (T_PTS - 32));
            float f[C_IN]; float mx = -INFINITY;
            if (act) {
                const float* fp = fv + (32 + lane) * C_IN;
#pragma unroll
                for (int c = 0; c < C_IN; c++) { f[c] = fp[c]; mx = fmaxf(mx, f[c]); }
            }
            bool msk = act && (mx != 0.0f);
            mb1 = __ballot_sync(0xFFFFFFFFu, msk);
            if (msk) {
                int rank = __popc(mb0) + __popc(mb1 & ((1u << lane) - 1u));
                float h[U1];
#pragma unroll
                for (int u = 0; u < U1; u++) {
                    float a = sb1[u];
#pragma unroll
                    for (int c = 0; c < C_IN; c++) a = fmaf(f[c], sw1[c * U1 + u], a);
                    a = fmaxf(a, 0.f);
                    h[u] = fmaf(a, s_sc1[u], s_sh1[u]);
                }
                float4* row = (float4*)&s_h1[w][rank][0];
                row[0] = make_float4(h[0],  h[1],  h[2],  h[3]);
                row[1] = make_float4(h[4],  h[5],  h[6],  h[7]);
                row[2] = make_float4(h[8],  h[9],  h[10], h[11]);
                row[3] = make_float4(h[12], h[13], h[14], h[15]);
            }
        }
        const int nm = __popc(mb0) + __popc(mb1);
        const int nz = T_PTS - nm;
        __syncwarp();

        if (lane < U1) {
            float mx = (nz > 0) ? s_h1z[lane] : -INFINITY;
            for (int r = 0; r < nm; r++) mx = fmaxf(mx, s_h1[w][r][lane]);
            s_agg[w][lane] = mx;
        }
        __syncwarp();

        float aggdot = b2l;
#pragma unroll
        for (int j = 0; j < U1; j++)
            aggdot = fmaf(s_agg[w][j], wagg[j], aggdot);

        float Mx1 = -INFINITY, Mn1 = INFINITY;
        {
            float fz = (float)nz;
            vsum += fz * h2z;
            vsq   = fmaf(fz, h2z * h2z, vsq);
        }

        int r = 0;
        for (; r + 2 <= nm; r += 2) {
            const float4* ra = (const float4*)&s_h1[w][r][0];
            const float4* rb = (const float4*)&s_h1[w][r + 1][0];
            float4 a0 = ra[0], a1 = ra[1], a2 = ra[2], a3 = ra[3];
            float4 c0 = rb[0], c1 = rb[1], c2 = rb[2], c3 = rb[3];
            float d0 = a0.x * wcol[0], d1 = a0.y * wcol[1];
            float e0 = c0.x * wcol[0], e1 = c0.y * wcol[1];
            d0 = fmaf(a0.z, wcol[2],  d0); d1 = fmaf(a0.w, wcol[3],  d1);
            e0 = fmaf(c0.z, wcol[2],  e0); e1 = fmaf(c0.w, wcol[3],  e1);
            d0 = fmaf(a1.x, wcol[4],  d0); d1 = fmaf(a1.y, wcol[5],  d1);
            e0 = fmaf(c1.x, wcol[4],  e0); e1 = fmaf(c1.y, wcol[5],  e1);
            d0 = fmaf(a1.z, wcol[6],  d0); d1 = fmaf(a1.w, wcol[7],  d1);
            e0 = fmaf(c1.z, wcol[6],  e0); e1 = fmaf(c1.w, wcol[7],  e1);
            d0 = fmaf(a2.x, wcol[8],  d0); d1 = fmaf(a2.y, wcol[9],  d1);
            e0 = fmaf(c2.x, wcol[8],  e0); e1 = fmaf(c2.y, wcol[9],  e1);
            d0 = fmaf(a2.z, wcol[10], d0); d1 = fmaf(a2.w, wcol[11], d1);
            e0 = fmaf(c2.z, wcol[10], e0); e1 = fmaf(c2.w, wcol[11], e1);
            d0 = fmaf(a3.x, wcol[12], d0); d1 = fmaf(a3.y, wcol[13], d1);
            e0 = fmaf(c3.x, wcol[12], e0); e1 = fmaf(c3.y, wcol[13], e1);
            d0 = fmaf(a3.z, wcol[14], d0); d1 = fmaf(a3.w, wcol[15], d1);
            e0 = fmaf(c3.z, wcol[14], e0); e1 = fmaf(c3.w, wcol[15], e1);
            float h2a = fmaxf(d0 + d1 + aggdot, 0.f);
            float h2b = fmaxf(e0 + e1 + aggdot, 0.f);
            vsum += h2a + h2b;
            vsq   = fmaf(h2a, h2a, vsq); vsq = fmaf(h2b, h2b, vsq);
            Mx1 = fmaxf(Mx1, fmaxf(h2a, h2b));
            Mn1 = fminf(Mn1, fminf(h2a, h2b));
        }
        if (r < nm) {
            const float4* ra = (const float4*)&s_h1[w][r][0];
            float4 a0 = ra[0], a1 = ra[1], a2 = ra[2], a3 = ra[3];
            float d0 = a0.x * wcol[0], d1 = a0.y * wcol[1];
            d0 = fmaf(a0.z, wcol[2],  d0); d1 = fmaf(a0.w, wcol[3],  d1);
            d0 = fmaf(a1.x, wcol[4],  d0); d1 = fmaf(a1.y, wcol[5],  d1);
            d0 = fmaf(a1.z, wcol[6],  d0); d1 = fmaf(a1.w, wcol[7],  d1);
            d0 = fmaf(a2.x, wcol[8],  d0); d1 = fmaf(a2.y, wcol[9],  d1);
            d0 = fmaf(a2.z, wcol[10], d0); d1 = fmaf(a2.w, wcol[11], d1);
            d0 = fmaf(a3.x, wcol[12], d0); d1 = fmaf(a3.y, wcol[13], d1);
            d0 = fmaf(a3.z, wcol[14], d0); d1 = fmaf(a3.w, wcol[15], d1);
            float h2a = fmaxf(d0 + d1 + aggdot, 0.f);
            vsum += h2a;
            vsq   = fmaf(h2a, h2a, vsq);
            Mx1 = fmaxf(Mx1, h2a);
            Mn1 = fminf(Mn1, h2a);
        }
        float Mx = (nz > 0) ? fmaxf(Mx1, h2z) : Mx1;
        float Mn = (nz > 0) ? fminf(Mn1, h2z) : Mn1;

        float* gv = g_vox + (size_t)v * (4 * U2);
        gv[lane]          = Mx;
        gv[U2 + lane]     = Mn;
        gv[2 * U2 + lane] = Mx1;
        gv[3 * U2 + lane] = Mn1;
        if (lane == 0) g_flags[v] = ((nm > 0) ? 1 : 0) | ((nm == T_PTS) ? 2 : 0);
    }

    // BN2 stats: block reduce then one atomic per channel
    atomicAdd(&bsum[lane], vsum);
    atomicAdd(&bsq [lane], vsq);
    __syncthreads();
    if (tid < U2) {
        atomicAdd(&g_sum2[tid], bsum[tid]);
        atomicAdd(&g_sq2 [tid], bsq [tid]);
    }
}

// ---------------- pass 3: finalize BN2 + scatter ----------------
__global__ void __launch_bounds__(256)
scatter_kernel(const float* __restrict__ g2, const float* __restrict__ be2,
               const int* __restrict__ coord, float* __restrict__ out) {
    __shared__ float s_sc2[U2], s_sh2[U2];
    const int tid  = threadIdx.x;
    const int w    = tid >> 5;
    const int lane = tid & 31;
    const float invN = 1.0f / (float)NROWS;

    if (tid < U2) {
        float mean = g_sum2[tid] * invN;
        float var  = g_sq2 [tid] * invN - mean * mean;
        float sc   = rsqrtf(var + EPSBN) * g2[tid];
        s_sc2[tid] = sc;
        s_sh2[tid] = be2[tid] - mean * sc;
    }
    __syncthreads();

    const float sc = s_sc2[lane];
    const float sh = s_sh2[lane];
    const int v = blockIdx.x * 8 + w;   // grid covers K_VOX exactly

    const float* gv = g_vox + (size_t)v * (4 * U2);
    float Mx  = __ldcg(gv + lane);
    float Mn  = __ldcg(gv + U2 + lane);
    float Mx1 = __ldcg(gv + 2 * U2 + lane);
    float Mn1 = __ldcg(gv + 3 * U2 + lane);
    int   fl  = g_flags[v];
    bool anyM = (fl & 1) != 0;
    bool allM = (fl & 2) != 0;

    float agg2 = fmaf((sc >= 0.f) ? Mx  : Mn,  sc, sh);
    float mskd = fmaf((sc >= 0.f) ? Mx1 : Mn1, sc, sh);

    float vwlo = anyM ? mskd : -INFINITY;
    float vwhi = anyM ? agg2 : -INFINITY;
    if (!allM) { vwlo = fmaxf(vwlo, 0.f); vwhi = fmaxf(vwhi, 0.f); }

    const int* cp = coord + (size_t)v * 4;
    size_t base = ((((size_t)cp[0] * DD + cp[1]) * HH + cp[2]) * WW + cp[3]) * (size_t)(2 * U2);
    atomicAdd(out + base + lane,      vwlo);
    atomicAdd(out + base + U2 + lane, vwhi);
}

// ---------------- launch ----------------
extern "C" void kernel_launch(void* const* d_in, const int* in_sizes, int n_in,
                              void* d_out, int out_size) {
    const float* feat  = (const float*)d_in[0];
    const float* w1    = (const float*)d_in[1];
    const float* b1    = (const float*)d_in[2];
    const float* g1    = (const float*)d_in[3];
    const float* be1   = (const float*)d_in[4];
    const float* w2    = (const float*)d_in[5];
    const float* b2    = (const float*)d_in[6];
    const float* g2    = (const float*)d_in[7];
    const float* be2   = (const float*)d_in[8];
    const int*   coord = (const int*)  d_in[9];
    float* out = (float*)d_out;

    // fork: driver memset runs on s2, concurrent with compute
    cudaEventRecord(g_ctx.ev_fork, 0);
    cudaStreamWaitEvent(g_ctx.s2, g_ctx.ev_fork, 0);
    cudaMemsetAsync(d_out, 0, (size_t)out_size * sizeof(float), g_ctx.s2);
    cudaEventRecord(g_ctx.ev_join, g_ctx.s2);

    // compute chain: reset + single persistent kernel (1 block/SM -> leaves
    // nearly all SM block/thread slots to the memset kernel)
    reset_kernel<<<1, 64>>>();
    compute_kernel<<<NBLK, VW * 32>>>(feat, g1, be1, w1, b1, w2, b2);

    // join: scatter needs both the zeroed grid and the voxel results
    cudaStreamWaitEvent(0, g_ctx.ev_join, 0);
    scatter_kernel<<<K_VOX / 8, 256>>>(g2, be2, coord, out);
}

// round 8
// speedup vs baseline: 1.3815x; 1.0159x over previous
#include <cuda_runtime.h>
#include <math.h>

#define K_VOX 40000
#define T_PTS 35
#define C_IN  7
#define U1    16
#define U2    32
#define DD    10
#define HH    400
#define WW    352
#define NROWS (K_VOX * T_PTS)
#define EPSBN 1e-5f
#define H1S   20            // h1 row stride (floats)

#define NBLK  148           // persistent blocks, 1 per SM
#define VW    8             // warps per block

// region of the output zeroed by the compute kernel itself (floats)
#define R_ZELEMS (48u * 1024u * 1024u)        // 192 MB
#define R_Z4     (R_ZELEMS / 4u)              // float4 count (exact)
#define ZCHUNK   2048u                        // float4 per chunk (32 KB)

// ---------------- global scratch (static, allocation-free) ----------------
__device__ float    g_sum1[U1], g_sq1[U1];
__device__ float    g_sum2[U2], g_sq2[U2];
__device__ unsigned g_bar1;
__device__ unsigned g_zctr;
__device__ float    g_vox[(size_t)K_VOX * 4 * U2];  // [v][{Mx,Mn,Mx1,Mn1}][32]
__device__ int      g_flags[K_VOX];                 // bit0 anyM, bit1 allM

// ---------------- host-side fork/join resources (static init, no device mem) ----
namespace {
struct HostCtx {
    cudaStream_t zs[4];
    cudaEvent_t  ev_fork;
    cudaEvent_t  ev_z[4];
    HostCtx() {
        for (int i = 0; i < 4; i++) {
            cudaStreamCreateWithFlags(&zs[i], cudaStreamNonBlocking);
            cudaEventCreateWithFlags(&ev_z[i], cudaEventDisableTiming);
        }
        cudaEventCreateWithFlags(&ev_fork, cudaEventDisableTiming);
    }
};
HostCtx g_ctx;
}

__global__ void reset_kernel() {
    int t = threadIdx.x;
    if (t < U1) { g_sum1[t] = 0.f; g_sq1[t] = 0.f; }
    if (t < U2) { g_sum2[t] = 0.f; g_sq2[t] = 0.f; }
    if (t == 0) { g_bar1 = 0u; g_zctr = 0u; }
}

// grid barrier: all NBLK blocks resident by construction (1 block/SM)
__device__ __forceinline__ void gsync() {
    __syncthreads();
    if (threadIdx.x == 0) {
        __threadfence();
        atomicAdd(&g_bar1, 1u);
        while (*((volatile unsigned*)&g_bar1) < NBLK) { }
        __threadfence();
    }
    __syncthreads();
}

// per-warp: grab 32KB chunks of the [0, R_Z4) float4 range and zero them
__device__ __forceinline__ void zero_chunks(float4* o4, int lane) {
    const float4 z = make_float4(0.f, 0.f, 0.f, 0.f);
    for (;;) {
        unsigned c;
        if (lane == 0) c = atomicAdd(&g_zctr, 1u);
        c = __shfl_sync(0xFFFFFFFFu, c, 0);
        size_t base = (size_t)c * ZCHUNK;
        if (base >= R_Z4) break;
        float4* p = o4 + base + lane;
#pragma unroll
        for (int i = 0; i < (int)(ZCHUNK / 32); i++)
            p[(size_t)i * 32] = z;            // STG.128 [reg+imm]
    }
}

// ---------------- persistent compute: BN1 stats + voxel pass + zero help ----
__global__ void __launch_bounds__(VW * 32, 1)
compute_kernel(const float* __restrict__ feat,
               const float* __restrict__ g1,  const float* __restrict__ be1,
               const float* __restrict__ w1,  const float* __restrict__ b1,
               const float* __restrict__ w2,  const float* __restrict__ b2,
               float* __restrict__ out) {
    __shared__ float sw1[C_IN * U1];
    __shared__ float sb1[U1];
    __shared__ float s_sc1[U1], s_sh1[U1], s_h1z[U1];
    __shared__ float ssum[U1], ssq[U1];
    __shared__ float s_h1[VW][T_PTS][H1S];
    __shared__ float s_agg[VW][U1];

    const int tid  = threadIdx.x;
    const int w    = tid >> 5;
    const int lane = tid & 31;
    const int bid  = blockIdx.x;
    const float invN = 1.0f / (float)NROWS;

    if (tid < C_IN * U1) sw1[tid] = w1[tid];
    if (tid < U1) { sb1[tid] = b1[tid]; ssum[tid] = 0.f; ssq[tid] = 0.f; }
    __syncthreads();

    // ===== stage 1: BN1 statistics =====
    {
        float psum[U1], psq[U1];
#pragma unroll
        for (int u = 0; u < U1; u++) { psum[u] = 0.f; psq[u] = 0.f; }
        for (int r = bid * (VW * 32) + tid; r < NROWS; r += NBLK * (VW * 32)) {
            const float* fp = feat + (size_t)r * C_IN;
            float f[C_IN];
#pragma unroll
            for (int c = 0; c < C_IN; c++) f[c] = fp[c];
#pragma unroll
            for (int u = 0; u < U1; u++) {
                float a = sb1[u];
#pragma unroll
                for (int c = 0; c < C_IN; c++) a = fmaf(f[c], sw1[c * U1 + u], a);
                a = fmaxf(a, 0.f);
                psum[u] += a;
                psq [u]  = fmaf(a, a, psq[u]);
            }
        }
#pragma unroll
        for (int u = 0; u < U1; u++) {
#pragma unroll
            for (int o = 16; o > 0; o >>= 1) {
                psum[u] += __shfl_down_sync(0xFFFFFFFFu, psum[u], o);
                psq [u] += __shfl_down_sync(0xFFFFFFFFu, psq [u], o);
            }
            if (lane == 0) { atomicAdd(&ssum[u], psum[u]); atomicAdd(&ssq[u], psq[u]); }
        }
        __syncthreads();
        if (tid < U1) {
            atomicAdd(&g_sum1[tid], ssum[tid]);
            atomicAdd(&g_sq1 [tid], ssq [tid]);
        }
    }
    gsync();

    // fold BN1 into scale/shift
    if (tid < U1) {
        float mean = __ldcg(&g_sum1[tid]) * invN;
        float var  = __ldcg(&g_sq1 [tid]) * invN - mean * mean;
        float sc   = rsqrtf(var + EPSBN) * g1[tid];
        s_sc1[tid] = sc;
        float sh   = be1[tid] - mean * sc;
        s_sh1[tid] = sh;
        s_h1z[tid] = fmaf(fmaxf(sb1[tid], 0.f), sc, sh);
    }
    __syncthreads();

    // ===== stage 2: voxel loop (1 warp = 1 voxel per iteration) =====
    const float b2l = b2[lane];
    const float h2z = fmaxf(b2l, 0.f);
    float wcol[U1];
#pragma unroll
    for (int i = 0; i < U1; i++) wcol[i] = w2[i * U2 + lane];
    float wagg[U1];
#pragma unroll
    for (int i = 0; i < U1; i++) wagg[i] = w2[(U1 + i) * U2 + lane];

    float vsum = 0.f, vsq = 0.f;

    for (int v = bid * VW + w; v < K_VOX; v += NBLK * VW) {
        const float* fv = feat + (size_t)v * T_PTS * C_IN;

        unsigned mb0, mb1;
        {   // rows t = lane
            const float* fp = fv + lane * C_IN;
            float f[C_IN]; float mx = -INFINITY;
#pragma unroll
            for (int c = 0; c < C_IN; c++) { f[c] = fp[c]; mx = fmaxf(mx, f[c]); }
            bool msk = (mx != 0.0f);
            mb0 = __ballot_sync(0xFFFFFFFFu, msk);
            if (msk) {
                int rank = __popc(mb0 & ((1u << lane) - 1u));
                float h[U1];
#pragma unroll
                for (int u = 0; u < U1; u++) {
                    float a = sb1[u];
#pragma unroll
                    for (int c = 0; c < C_IN; c++) a = fmaf(f[c], sw1[c * U1 + u], a);
                    a = fmaxf(a, 0.f);
                    h[u] = fmaf(a, s_sc1[u], s_sh1[u]);
                }
                float4* row = (float4*)&s_h1[w][rank][0];
                row[0] = make_float4(h[0],  h[1],  h[2],  h[3]);
                row[1] = make_float4(h[4],  h[5],  h[6],  h[7]);
                row[2] = make_float4(h[8],  h[9],  h[10], h[11]);
                row[3] = make_float4(h[12], h[13], h[14], h[15]);
            }
        }
        {   // rows t = 32 + lane (3 valid)
            bool act = (lane < (T_PTS - 32));
            float f[C_IN]; float mx = -INFINITY;
            if (act) {
                const float* fp = fv + (32 + lane) * C_IN;
#pragma unroll
                for (int c = 0; c < C_IN; c++) { f[c] = fp[c]; mx = fmaxf(mx, f[c]); }
            }
            bool msk = act && (mx != 0.0f);
            mb1 = __ballot_sync(0xFFFFFFFFu, msk);
            if (msk) {
                int rank = __popc(mb0) + __popc(mb1 & ((1u << lane) - 1u));
                float h[U1];
#pragma unroll
                for (int u = 0; u < U1; u++) {
                    float a = sb1[u];
#pragma unroll
                    for (int c = 0; c < C_IN; c++) a = fmaf(f[c], sw1[c * U1 + u], a);
                    a = fmaxf(a, 0.f);
                    h[u] = fmaf(a, s_sc1[u], s_sh1[u]);
                }
                float4* row = (float4*)&s_h1[w][rank][0];
                row[0] = make_float4(h[0],  h[1],  h[2],  h[3]);
                row[1] = make_float4(h[4],  h[5],  h[6],  h[7]);
                row[2] = make_float4(h[8],  h[9],  h[10], h[11]);
                row[3] = make_float4(h[12], h[13], h[14], h[15]);
            }
        }
        const int nm = __popc(mb0) + __popc(mb1);
        const int nz = T_PTS - nm;
        __syncwarp();

        if (lane < U1) {
            float mx = (nz > 0) ? s_h1z[lane] : -INFINITY;
            for (int r = 0; r < nm; r++) mx = fmaxf(mx, s_h1[w][r][lane]);
            s_agg[w][lane] = mx;
        }
        __syncwarp();

        float aggdot = b2l;
#pragma unroll
        for (int j = 0; j < U1; j++)
            aggdot = fmaf(s_agg[w][j], wagg[j], aggdot);

        float Mx1 = -INFINITY, Mn1 = INFINITY;
        {
            float fz = (float)nz;
            vsum += fz * h2z;
            vsq   = fmaf(fz, h2z * h2z, vsq);
        }

        int r = 0;
        for (; r + 2 <= nm; r += 2) {
            const float4* ra = (const float4*)&s_h1[w][r][0];
            const float4* rb = (const float4*)&s_h1[w][r + 1][0];
            float4 a0 = ra[0], a1 = ra[1], a2 = ra[2], a3 = ra[3];
            float4 c0 = rb[0], c1 = rb[1], c2 = rb[2], c3 = rb[3];
            float d0 = a0.x * wcol[0], d1 = a0.y * wcol[1];
            float e0 = c0.x * wcol[0], e1 = c0.y * wcol[1];
            d0 = fmaf(a0.z, wcol[2],  d0); d1 = fmaf(a0.w, wcol[3],  d1);
            e0 = fmaf(c0.z, wcol[2],  e0); e1 = fmaf(c0.w, wcol[3],  e1);
            d0 = fmaf(a1.x, wcol[4],  d0); d1 = fmaf(a1.y, wcol[5],  d1);
            e0 = fmaf(c1.x, wcol[4],  e0); e1 = fmaf(c1.y, wcol[5],  e1);
            d0 = fmaf(a1.z, wcol[6],  d0); d1 = fmaf(a1.w, wcol[7],  d1);
            e0 = fmaf(c1.z, wcol[6],  e0); e1 = fmaf(c1.w, wcol[7],  e1);
            d0 = fmaf(a2.x, wcol[8],  d0); d1 = fmaf(a2.y, wcol[9],  d1);
            e0 = fmaf(c2.x, wcol[8],  e0); e1 = fmaf(c2.y, wcol[9],  e1);
            d0 = fmaf(a2.z, wcol[10], d0); d1 = fmaf(a2.w, wcol[11], d1);
            e0 = fmaf(c2.z, wcol[10], e0); e1 = fmaf(c2.w, wcol[11], e1);
            d0 = fmaf(a3.x, wcol[12], d0); d1 = fmaf(a3.y, wcol[13], d1);
            e0 = fmaf(c3.x, wcol[12], e0); e1 = fmaf(c3.y, wcol[13], e1);
            d0 = fmaf(a3.z, wcol[14], d0); d1 = fmaf(a3.w, wcol[15], d1);
            e0 = fmaf(c3.z, wcol[14], e0); e1 = fmaf(c3.w, wcol[15], e1);
            float h2a = fmaxf(d0 + d1 + aggdot, 0.f);
            float h2b = fmaxf(e0 + e1 + aggdot, 0.f);
            vsum += h2a + h2b;
            vsq   = fmaf(h2a, h2a, vsq); vsq = fmaf(h2b, h2b, vsq);
            Mx1 = fmaxf(Mx1, fmaxf(h2a, h2b));
            Mn1 = fminf(Mn1, fminf(h2a, h2b));
        }
        if (r < nm) {
            const float4* ra = (const float4*)&s_h1[w][r][0];
            float4 a0 = ra[0], a1 = ra[1], a2 = ra[2], a3 = ra[3];
            float d0 = a0.x * wcol[0], d1 = a0.y * wcol[1];
            d0 = fmaf(a0.z, wcol[2],  d0); d1 = fmaf(a0.w, wcol[3],  d1);
            d0 = fmaf(a1.x, wcol[4],  d0); d1 = fmaf(a1.y, wcol[5],  d1);
            d0 = fmaf(a1.z, wcol[6],  d0); d1 = fmaf(a1.w, wcol[7],  d1);
            d0 = fmaf(a2.x, wcol[8],  d0); d1 = fmaf(a2.y, wcol[9],  d1);
            d0 = fmaf(a2.z, wcol[10], d0); d1 = fmaf(a2.w, wcol[11], d1);
            d0 = fmaf(a3.x, wcol[12], d0); d1 = fmaf(a3.y, wcol[13], d1);
            d0 = fmaf(a3.z, wcol[14], d0); d1 = fmaf(a3.w, wcol[15], d1);
            float h2a = fmaxf(d0 + d1 + aggdot, 0.f);
            vsum += h2a;
            vsq   = fmaf(h2a, h2a, vsq);
            Mx1 = fmaxf(Mx1, h2a);
            Mn1 = fminf(Mn1, h2a);
        }
        float Mx = (nz > 0) ? fmaxf(Mx1, h2z) : Mx1;
        float Mn = (nz > 0) ? fminf(Mn1, h2z) : Mn1;

        float* gv = g_vox + (size_t)v * (4 * U2);
        gv[lane]          = Mx;
        gv[U2 + lane]     = Mn;
        gv[2 * U2 + lane] = Mx1;
        gv[3 * U2 + lane] = Mn1;
        if (lane == 0) g_flags[v] = ((nm > 0) ? 1 : 0) | ((nm == T_PTS) ? 2 : 0);
    }

    // per-warp BN2 stat atomics (no block sync -> warps start zeroing ASAP)
    atomicAdd(&g_sum2[lane], vsum);
    atomicAdd(&g_sq2 [lane], vsq);

    // this warp is done with voxels -> zero its share of [0, R_ZELEMS)
    zero_chunks((float4*)out, lane);
}

// ---------------- pass 3: finalize BN2 + scatter ----------------
__global__ void __launch_bounds__(256)
scatter_kernel(const float* __restrict__ g2, const float* __restrict__ be2,
               const int* __restrict__ coord, float* __restrict__ out) {
    __shared__ float s_sc2[U2], s_sh2[U2];
    const int tid  = threadIdx.x;
    const int w    = tid >> 5;
    const int lane = tid & 31;
    const float invN = 1.0f / (float)NROWS;

    if (tid < U2) {
        float mean = g_sum2[tid] * invN;
        float var  = g_sq2 [tid] * invN - mean * mean;
        float sc   = rsqrtf(var + EPSBN) * g2[tid];
        s_sc2[tid] = sc;
        s_sh2[tid] = be2[tid] - mean * sc;
    }
    __syncthreads();

    const float sc = s_sc2[lane];
    const float sh = s_sh2[lane];
    const int v = blockIdx.x * 8 + w;   // grid covers K_VOX exactly

    const float* gv = g_vox + (size_t)v * (4 * U2);
    float Mx  = __ldcg(gv + lane);
    float Mn  = __ldcg(gv + U2 + lane);
    float Mx1 = __ldcg(gv + 2 * U2 + lane);
    float Mn1 = __ldcg(gv + 3 * U2 + lane);
    int   fl  = g_flags[v];
    bool anyM = (fl & 1) != 0;
    bool allM = (fl & 2) != 0;

    float agg2 = fmaf((sc >= 0.f) ? Mx  : Mn,  sc, sh);
    float mskd = fmaf((sc >= 0.f) ? Mx1 : Mn1, sc, sh);

    float vwlo = anyM ? mskd : -INFINITY;
    float vwhi = anyM ? agg2 : -INFINITY;
    if (!allM) { vwlo = fmaxf(vwlo, 0.f); vwhi = fmaxf(vwhi, 0.f); }

    const int* cp = coord + (size_t)v * 4;
    size_t base = ((((size_t)cp[0] * DD + cp[1]) * HH + cp[2]) * WW + cp[3]) * (size_t)(2 * U2);
    atomicAdd(out + base + lane,      vwlo);
    atomicAdd(out + base + U2 + lane, vwhi);
}

// ---------------- launch ----------------
extern "C" void kernel_launch(void* const* d_in, const int* in_sizes, int n_in,
                              void* d_out, int out_size) {
    const float* feat  = (const float*)d_in[0];
    const float* w1    = (const float*)d_in[1];
    const float* b1    = (const float*)d_in[2];
    const float* g1    = (const float*)d_in[3];
    const float* be1   = (const float*)d_in[4];
    const float* w2    = (const float*)d_in[5];
    const float* b2    = (const float*)d_in[6];
    const float* g2    = (const float*)d_in[7];
    const float* be2   = (const float*)d_in[8];
    const int*   coord = (const int*)  d_in[9];
    float* out = (float*)d_out;

    // fork: 4 concurrent driver memsets cover [R_ZELEMS, out_size)
    cudaEventRecord(g_ctx.ev_fork, 0);
    {
        size_t rem = (size_t)out_size - R_ZELEMS;
        size_t q   = rem / 4;
        for (int i = 0; i < 4; i++) {
            size_t beg = R_ZELEMS + (size_t)i * q;
            size_t cnt = (i == 3) ? (rem - 3 * q) : q;
            cudaStreamWaitEvent(g_ctx.zs[i], g_ctx.ev_fork, 0);
            cudaMemsetAsync(out + beg, 0, cnt * sizeof(float), g_ctx.zs[i]);
            cudaEventRecord(g_ctx.ev_z[i], g_ctx.zs[i]);
        }
    }

    // compute chain: reset + persistent kernel (also zeroes [0, R_ZELEMS))
    reset_kernel<<<1, 64>>>();
    compute_kernel<<<NBLK, VW * 32>>>(feat, g1, be1, w1, b1, w2, b2, out);

    // join: scatter needs the fully zeroed grid + voxel results
    for (int i = 0; i < 4; i++)
        cudaStreamWaitEvent(0, g_ctx.ev_z[i], 0);
    scatter_kernel<<<K_VOX / 8, 256>>>(g2, be2, coord, out);
}